// round 11
// baseline (speedup 1.0000x reference)
#include <cuda_runtime.h>
#include <cuda_bf16.h>
#include <math_constants.h>
#include <cstdint>

#define BETA_MIN 0.1f
#define BETA_MAX 20.0f
#define LOG2E 1.4426950408889634f
#define DDIM 128
#define NROWS 4096
#define MKEYS 16384
#define SPLITK 4
#define BM 128
#define BN 64
#define NT 64            // key tiles per CTA
#define TILES_ALL 256

// dynamic smem layout
#define XS 0                               // A tile fused hi/lo, 64KB
#define G1S(k) (65536 + ((k) & 1) * 32768) // GEMM1 blob slots, 32KB x2
#define G2S(k) (131072 + ((k) & 1) * 32768)// GEMM2 blob slots, 32KB x2
#define Y2S(k) (196608 + ((k) & 3) * 256)  // y2 slots, 256B x4
#define SMEM_BYTES 197632

__device__ float g_y2[MKEYS];
__device__ uint4 g_yc1[TILES_ALL * 2048];   // fused GEMM1 B blobs (hi+lo interleaved)
__device__ uint4 g_yc2[TILES_ALL * 2048];   // fused GEMM2 B blobs
__device__ float g_pO[(size_t)SPLITK * NROWS * DDIM];
__device__ float g_pm[SPLITK * NROWS];
__device__ float g_pl[SPLITK * NROWS];

// ---------------- helpers ----------------
__device__ __forceinline__ uint32_t smem_u32(const void* p) {
    uint32_t a;
    asm("{ .reg .u64 t; cvta.to.shared.u64 t, %1; cvt.u32.u64 %0, t; }" : "=r"(a) : "l"(p));
    return a;
}
__device__ __forceinline__ float ex2f(float v) {
    float r;
    asm("ex2.approx.f32 %0, %1;" : "=f"(r) : "f"(v));
    return r;
}
// fast 2^v for v <= 0 (merge kernel only)
__device__ __forceinline__ float fexp2(float v) {
    v = fmaxf(v, -30.0f);
    float r = v + 12582912.0f;
    int   n = __float_as_int(r) - 0x4B400000;
    float f = v - (r - 12582912.0f);
    float p = 1.3333558146e-3f;
    p = fmaf(p, f, 9.6181291918e-3f);
    p = fmaf(p, f, 5.5504108664e-2f);
    p = fmaf(p, f, 2.4022650696e-1f);
    p = fmaf(p, f, 6.9314718056e-1f);
    p = fmaf(p, f, 1.0f);
    return __int_as_float(__float_as_int(p) + (n << 23));
}
// split (a,b) -> bf16x2 hi (low half = a) + bf16x2 lo residual
__device__ __forceinline__ void split2(float a, float b, uint32_t& h, uint32_t& l) {
    uint32_t hp, lp;
    asm("cvt.rn.bf16x2.f32 %0, %1, %2;" : "=r"(hp) : "f"(b), "f"(a));
    float ra = a - __int_as_float(hp << 16);
    float rb = b - __int_as_float(hp & 0xFFFF0000u);
    asm("cvt.rn.bf16x2.f32 %0, %1, %2;" : "=r"(lp) : "f"(rb), "f"(ra));
    h = hp; l = lp;
}
__device__ __forceinline__ void mma16816(float* c, const uint32_t* a, uint32_t b0, uint32_t b1) {
    asm volatile("mma.sync.aligned.m16n8k16.row.col.f32.bf16.bf16.f32 "
        "{%0,%1,%2,%3}, {%4,%5,%6,%7}, {%8,%9}, {%0,%1,%2,%3};"
        : "+f"(c[0]), "+f"(c[1]), "+f"(c[2]), "+f"(c[3])
        : "r"(a[0]), "r"(a[1]), "r"(a[2]), "r"(a[3]), "r"(b0), "r"(b1));
}
__device__ __forceinline__ void cpa16(uint32_t s, const void* g) {
    asm volatile("cp.async.cg.shared.global [%0], [%1], 16;" :: "r"(s), "l"(g));
}
#define CP_COMMIT() asm volatile("cp.async.commit_group;" ::: "memory")
#define CP_WAIT0()  asm volatile("cp.async.wait_group 0;" ::: "memory")

__device__ __forceinline__ void pf_g1(uint32_t dst, int tg, int tid) {
    const uint4* s1 = g_yc1 + tg * 2048;
#pragma unroll
    for (int i = 0; i < 8; i++) { int idx = tid + 256 * i; cpa16(dst + idx * 16, s1 + idx); }
}
__device__ __forceinline__ void pf_g2(uint32_t dst, int tg, int tid) {
    const uint4* s2 = g_yc2 + tg * 2048;
#pragma unroll
    for (int i = 0; i < 8; i++) { int idx = tid + 256 * i; cpa16(dst + idx * 16, s2 + idx); }
}
__device__ __forceinline__ void pf_y2(uint32_t dst, int tg, int tid) {
    if (tid < 16) cpa16(dst + tid * 16, ((const uint4*)(g_y2 + tg * 64)) + tid);
}
// one K-chunk (k=16) of GEMM1: 24 MMAs into s[8][4]
__device__ __forceinline__ void g1_chunk(const uint8_t* g1buf, const uint8_t* arow1,
                                         const uint8_t* arow2, int lane, int rsub, int lq,
                                         int kc, float s[8][4]) {
    uint32_t oA = (uint32_t)((kc ^ rsub) * 64 + lq * 16);
    uint4 ua = *reinterpret_cast<const uint4*>(arow1 + oA);
    uint4 ub = *reinterpret_cast<const uint4*>(arow2 + oA);
    uint32_t ah[4] = { ua.x, ub.x, ua.y, ub.y };
    uint32_t al[4] = { ua.z, ub.z, ua.w, ub.w };
    const uint8_t* bbase = g1buf + kc * 4096 + lane * 16;
#pragma unroll
    for (int nf = 0; nf < 8; nf++) {
        uint4 bb = *reinterpret_cast<const uint4*>(bbase + nf * 512);
        mma16816(s[nf], ah, bb.x, bb.y);
        mma16816(s[nf], ah, bb.z, bb.w);
        mma16816(s[nf], al, bb.x, bb.y);
    }
}

// ---------------- precompute: y2 ----------------
__global__ void gmm_y2_kernel(const float* __restrict__ Y, int M) {
    int row = blockIdx.x * 8 + threadIdx.y;
    if (row >= M) return;
    int l = threadIdx.x;
    float4 v = *reinterpret_cast<const float4*>(Y + (size_t)row * DDIM + l * 4);
    float s = v.x * v.x + v.y * v.y + v.z * v.z + v.w * v.w;
#pragma unroll
    for (int off = 16; off > 0; off >>= 1) s += __shfl_xor_sync(0xffffffffu, s, off);
    if (l == 0) g_y2[row] = s;
}

// ---------------- precompute: fused split blobs (smem-staged) ----------------
__global__ void gmm_prep_kernel(const float* __restrict__ Y) {
    __shared__ float ys[BN * DDIM];
    const int tile = blockIdx.x, tid = threadIdx.x;
    const float* src = Y + (size_t)tile * BN * DDIM;
#pragma unroll
    for (int i = 0; i < 8; i++) {
        int idx = tid + 256 * i;
        *reinterpret_cast<float4*>(ys + idx * 4) =
            *reinterpret_cast<const float4*>(src + idx * 4);
    }
    __syncthreads();
#pragma unroll
    for (int j = 0; j < 8; j++) {
        int s = tid + 256 * j;
        int kc = s >> 8, nf = (s >> 5) & 7, rs = (s >> 2) & 7, q = s & 3;
        int n = nf * 8 + rs, kb = kc * 16 + q * 2;
        const float* row = ys + n * DDIM;
        uint32_t h0, l0, h1, l1;
        split2(row[kb], row[kb + 1], h0, l0);
        split2(row[kb + 8], row[kb + 9], h1, l1);
        g_yc1[tile * 2048 + s] = make_uint4(h0, h1, l0, l1);
    }
#pragma unroll
    for (int j = 0; j < 8; j++) {
        int s = tid + 256 * j;
        int kc2 = s >> 9, nf2 = (s >> 5) & 15, rs = (s >> 2) & 7, q = s & 3;
        int d = nf2 * 8 + rs, k = kc2 * 16 + q * 2;
        uint32_t h0, l0, h1, l1;
        split2(ys[k * DDIM + d], ys[(k + 1) * DDIM + d], h0, l0);
        split2(ys[(k + 8) * DDIM + d], ys[(k + 9) * DDIM + d], h1, l1);
        g_yc2[tile * 2048 + s] = make_uint4(h0, h1, l0, l1);
    }
}

// ---------------- main fused kernel ----------------
__global__ __launch_bounds__(256, 1)
void gmm_main_kernel(const float* __restrict__ X, const float* __restrict__ T) {
    extern __shared__ uint8_t sb[];
    __shared__ float sh_a2[BM], sh_b2[BM];

    const int tid = threadIdx.x, lane = tid & 31, wid = tid >> 5;
    const int rb = blockIdx.x >> 2, q = blockIdx.x & 3;
    const int r0 = rb * BM;
    const int rw = wid * 16;
    const int rsub = lane >> 2;
    const int lq = lane & 3;
    const uint32_t sb0 = smem_u32(sb);
    const int t0 = q * NT;

    // prologue prefetch: tiles 0,1 (G1+y2) + tile 0 (G2)
    pf_g1(sb0 + G1S(0), t0 + 0, tid);
    pf_g1(sb0 + G1S(1), t0 + 1, tid);
    pf_y2(sb0 + Y2S(0), t0 + 0, tid);
    pf_y2(sb0 + Y2S(1), t0 + 1, tid);
    pf_g2(sb0 + G2S(0), t0 + 0, tid);
    CP_COMMIT();

    if (tid < BM) {
        float tv = T[r0 + tid];
        float lm = -0.25f * tv * tv * (BETA_MAX - BETA_MIN) - 0.5f * tv * BETA_MIN;
        float mean = expf(lm);
        float var = fmaxf(1.0f - expf(2.0f * lm), 1e-12f);
        float iv = 1.0f / var;
        sh_a2[tid] = mean * iv * LOG2E;
        sh_b2[tid] = -0.5f * mean * mean * iv * LOG2E;
    }
    __syncthreads();

    // Build A = a2_r * x_r, fused hi/lo layout (row*512 + (kc^(row&7))*64 + q*16)
    {
        int row = tid >> 1, half = tid & 1;
        float a2 = sh_a2[row];
        const float* src = X + (size_t)(r0 + row) * DDIM;
        uint8_t* abase = sb + XS + row * 512;
#pragma unroll
        for (int kc = half * 4; kc < half * 4 + 4; kc++) {
#pragma unroll
            for (int qq = 0; qq < 4; qq++) {
                int d = kc * 16 + qq * 2;
                float2 v0 = *reinterpret_cast<const float2*>(src + d);
                float2 v1 = *reinterpret_cast<const float2*>(src + d + 8);
                uint32_t h0, l0, h1, l1;
                split2(a2 * v0.x, a2 * v0.y, h0, l0);
                split2(a2 * v1.x, a2 * v1.y, h1, l1);
                *reinterpret_cast<uint4*>(abase + ((kc ^ (row & 7)) * 64 + qq * 16)) =
                    make_uint4(h0, h1, l0, l1);
            }
        }
    }

    const float b2a = sh_b2[rw + rsub];
    const float b2b = sh_b2[rw + rsub + 8];
    const uint8_t* arow1 = sb + XS + (rw + rsub) * 512;
    const uint8_t* arow2 = arow1 + 8 * 512;

    float o[16][4];
#pragma unroll
    for (int i = 0; i < 16; i++)
#pragma unroll
        for (int j = 0; j < 4; j++) o[i][j] = 0.0f;
    float m_a = -CUDART_INF_F, m_b = -CUDART_INF_F, l_a = 0.0f, l_b = 0.0f;

    // wait tile 0, then G1(0) -> s_cur
    CP_WAIT0();
    __syncthreads();
    float s_cur[8][4];
#pragma unroll
    for (int i = 0; i < 8; i++)
#pragma unroll
        for (int j = 0; j < 4; j++) s_cur[i][j] = 0.0f;
#pragma unroll
    for (int kc = 0; kc < 8; kc++)
        g1_chunk(sb + G1S(0), arow1, arow2, lane, rsub, lq, kc, s_cur);

    for (int kt = 0; kt < NT; kt++) {
        const bool havenext = (kt + 1 < NT);
        // single barrier per tile: all cp groups drained, all warps past last tile
        CP_WAIT0();
        __syncthreads();
        // prefetch: G1+y2 distance 2, G2 distance 1
        if (kt + 2 < NT) {
            pf_g1(sb0 + G1S(kt + 2), t0 + kt + 2, tid);
            pf_y2(sb0 + Y2S(kt + 2), t0 + kt + 2, tid);
        }
        if (havenext) pf_g2(sb0 + G2S(kt + 1), t0 + kt + 1, tid);
        CP_COMMIT();

        // ---- phase 1: bias + row max on s_cur ----
        const float* y2p = (const float*)(sb + Y2S(kt));
        float mxa = -CUDART_INF_F, mxb = -CUDART_INF_F;
#pragma unroll
        for (int f = 0; f < 8; f++) {
            float2 y2v = *reinterpret_cast<const float2*>(y2p + f * 8 + lq * 2);
            s_cur[f][0] = fmaf(b2a, y2v.x, s_cur[f][0]);
            s_cur[f][1] = fmaf(b2a, y2v.y, s_cur[f][1]);
            s_cur[f][2] = fmaf(b2b, y2v.x, s_cur[f][2]);
            s_cur[f][3] = fmaf(b2b, y2v.y, s_cur[f][3]);
            mxa = fmaxf(mxa, fmaxf(s_cur[f][0], s_cur[f][1]));
            mxb = fmaxf(mxb, fmaxf(s_cur[f][2], s_cur[f][3]));
        }
        mxa = fmaxf(mxa, __shfl_xor_sync(0xffffffffu, mxa, 1));
        mxa = fmaxf(mxa, __shfl_xor_sync(0xffffffffu, mxa, 2));
        mxb = fmaxf(mxb, __shfl_xor_sync(0xffffffffu, mxb, 1));
        mxb = fmaxf(mxb, __shfl_xor_sync(0xffffffffu, mxb, 2));
        float mna = fmaxf(m_a, mxa), mnb = fmaxf(m_b, mxb);
        float ala = ex2f(m_a - mna), alb = ex2f(m_b - mnb);
        m_a = mna; m_b = mnb;

        // ---- phase 2: exp/split(kt) interleaved with GEMM1(kt+1) ----
        float s_nxt[8][4];
#pragma unroll
        for (int i = 0; i < 8; i++)
#pragma unroll
            for (int j = 0; j < 4; j++) s_nxt[i][j] = 0.0f;
        const uint8_t* g1nb = sb + G1S(kt + 1);

        float suma = 0.0f, sumb = 0.0f;
        uint32_t ph[16], pl[16];
#pragma unroll
        for (int f = 0; f < 8; f++) {
            float p0 = ex2f(s_cur[f][0] - mna), p1 = ex2f(s_cur[f][1] - mna);
            float p2 = ex2f(s_cur[f][2] - mnb), p3 = ex2f(s_cur[f][3] - mnb);
            suma += p0 + p1; sumb += p2 + p3;
            split2(p0, p1, ph[2 * f], pl[2 * f]);
            split2(p2, p3, ph[2 * f + 1], pl[2 * f + 1]);
            if (havenext)
                g1_chunk(g1nb, arow1, arow2, lane, rsub, lq, f, s_nxt);
        }
        suma += __shfl_xor_sync(0xffffffffu, suma, 1);
        suma += __shfl_xor_sync(0xffffffffu, suma, 2);
        sumb += __shfl_xor_sync(0xffffffffu, sumb, 1);
        sumb += __shfl_xor_sync(0xffffffffu, sumb, 2);
        l_a = l_a * ala + suma;
        l_b = l_b * alb + sumb;

        // ---- phase 3: GEMM2(kt), nf2-outer with o-rescale folded in ----
        const uint8_t* g2b = sb + G2S(kt) + lane * 16;
#pragma unroll
        for (int nf2 = 0; nf2 < 16; nf2++) {
            o[nf2][0] *= ala; o[nf2][1] *= ala;
            o[nf2][2] *= alb; o[nf2][3] *= alb;
#pragma unroll
            for (int kc2 = 0; kc2 < 4; kc2++) {
                uint32_t ah[4] = { ph[4 * kc2], ph[4 * kc2 + 1], ph[4 * kc2 + 2], ph[4 * kc2 + 3] };
                uint32_t al_[4] = { pl[4 * kc2], pl[4 * kc2 + 1], pl[4 * kc2 + 2], pl[4 * kc2 + 3] };
                uint4 bb = *reinterpret_cast<const uint4*>(g2b + kc2 * 8192 + nf2 * 512);
                mma16816(o[nf2], ah, bb.x, bb.y);
                mma16816(o[nf2], ah, bb.z, bb.w);
                mma16816(o[nf2], al_, bb.x, bb.y);
            }
        }

        if (havenext) {
#pragma unroll
            for (int i = 0; i < 8; i++)
#pragma unroll
                for (int j = 0; j < 4; j++) s_cur[i][j] = s_nxt[i][j];
        }
    }

    // ---- write split partials ----
    {
        int ga = r0 + rw + rsub;
        int gbrow = ga + 8;
        if (lq == 0) {
            g_pm[q * NROWS + ga] = m_a;  g_pl[q * NROWS + ga] = l_a;
            g_pm[q * NROWS + gbrow] = m_b; g_pl[q * NROWS + gbrow] = l_b;
        }
        float* da = g_pO + ((size_t)(q * NROWS + ga)) * DDIM + lq * 2;
        float* db = g_pO + ((size_t)(q * NROWS + gbrow)) * DDIM + lq * 2;
#pragma unroll
        for (int nf = 0; nf < 16; nf++) {
            *reinterpret_cast<float2*>(da + nf * 8) = make_float2(o[nf][0], o[nf][1]);
            *reinterpret_cast<float2*>(db + nf * 8) = make_float2(o[nf][2], o[nf][3]);
        }
    }
}

// ---------------- merge splits + epilogue ----------------
__global__ void gmm_merge_kernel(const float* __restrict__ X, const float* __restrict__ T,
                                 float* __restrict__ out) {
    int row = blockIdx.x * 2 + (threadIdx.x >> 7);
    int d = threadIdx.x & 127;
    float tv = T[row];
    float lm = -0.25f * tv * tv * (BETA_MAX - BETA_MIN) - 0.5f * tv * BETA_MIN;
    float var = fmaxf(1.0f - expf(2.0f * lm), 1e-12f);
    float iv = 1.0f / var;
    float M = -CUDART_INF_F;
#pragma unroll
    for (int s = 0; s < SPLITK; s++) M = fmaxf(M, g_pm[s * NROWS + row]);
    float L = 0.0f, O = 0.0f;
#pragma unroll
    for (int s = 0; s < SPLITK; s++) {
        float w = fexp2(g_pm[s * NROWS + row] - M);
        L += g_pl[s * NROWS + row] * w;
        O += g_pO[((size_t)(s * NROWS + row)) * DDIM + d] * w;
    }
    out[(size_t)row * DDIM + d] = (O / L - X[(size_t)row * DDIM + d]) * iv;
}

// ---------------------------------------------------------------------------
extern "C" void kernel_launch(void* const* d_in, const int* in_sizes, int n_in,
                              void* d_out, int out_size) {
    (void)n_in; (void)out_size;
    const float* x = (const float*)d_in[0];
    const float* t = (const float*)d_in[1];
    const float* y = (const float*)d_in[2];
    float* out = (float*)d_out;
    int M = in_sizes[2] / DDIM;

    cudaFuncSetAttribute(gmm_main_kernel,
                         cudaFuncAttributeMaxDynamicSharedMemorySize, SMEM_BYTES);

    gmm_y2_kernel<<<(M + 7) / 8, dim3(32, 8)>>>(y, M);
    gmm_prep_kernel<<<TILES_ALL, 256>>>(y);
    gmm_main_kernel<<<(NROWS / BM) * SPLITK, 256, SMEM_BYTES>>>(x, t);
    gmm_merge_kernel<<<NROWS / 2, 256>>>(x, t, out);
}

// round 12
// speedup vs baseline: 1.5297x; 1.5297x over previous
#include <cuda_runtime.h>
#include <cuda_bf16.h>
#include <math_constants.h>
#include <cstdint>

#define BETA_MIN 0.1f
#define BETA_MAX 20.0f
#define LOG2E 1.4426950408889634f
#define DDIM 128
#define NROWS 4096
#define MKEYS 16384
#define SPLITK 4
#define BM 128
#define BN 64
#define NT 64            // key tiles per CTA (MKEYS/SPLITK/BN)
#define TILES_ALL 256

// smem layout
#define XS   0                 // A tile fused hi/lo: 128 rows * 512B = 64KB
#define BUF0 65536
#define BUFSTRIDE 66048        // 64KB blobs + 256B y2, 1KB aligned
#define B_G1 0                 // GEMM1 fused blob, 32KB
#define B_G2 32768             // GEMM2 fused blob, 32KB
#define B_Y2 65536
#define SMEM_BYTES (BUF0 + 2 * BUFSTRIDE)   // 197632

__device__ float g_y2[MKEYS];
__device__ uint4 g_yc1[TILES_ALL * 2048];   // fused GEMM1 B blobs (hi+lo interleaved)
__device__ uint4 g_yc2[TILES_ALL * 2048];   // fused GEMM2 B blobs
__device__ float g_pO[(size_t)SPLITK * NROWS * DDIM];
__device__ float g_pm[SPLITK * NROWS];
__device__ float g_pl[SPLITK * NROWS];

// ---------------- helpers ----------------
__device__ __forceinline__ uint32_t smem_u32(const void* p) {
    uint32_t a;
    asm("{ .reg .u64 t; cvta.to.shared.u64 t, %1; cvt.u32.u64 %0, t; }" : "=r"(a) : "l"(p));
    return a;
}
__device__ __forceinline__ float ex2f(float v) {
    float r;
    asm("ex2.approx.f32 %0, %1;" : "=f"(r) : "f"(v));
    return r;
}
// fast 2^v for v <= 0 (merge kernel only)
__device__ __forceinline__ float fexp2(float v) {
    v = fmaxf(v, -30.0f);
    float r = v + 12582912.0f;
    int   n = __float_as_int(r) - 0x4B400000;
    float f = v - (r - 12582912.0f);
    float p = 1.3333558146e-3f;
    p = fmaf(p, f, 9.6181291918e-3f);
    p = fmaf(p, f, 5.5504108664e-2f);
    p = fmaf(p, f, 2.4022650696e-1f);
    p = fmaf(p, f, 6.9314718056e-1f);
    p = fmaf(p, f, 1.0f);
    return __int_as_float(__float_as_int(p) + (n << 23));
}
// split (a,b) -> bf16x2 hi (low half = a) + bf16x2 lo residual
__device__ __forceinline__ void split2(float a, float b, uint32_t& h, uint32_t& l) {
    uint32_t hp, lp;
    asm("cvt.rn.bf16x2.f32 %0, %1, %2;" : "=r"(hp) : "f"(b), "f"(a));
    float ra = a - __int_as_float(hp << 16);
    float rb = b - __int_as_float(hp & 0xFFFF0000u);
    asm("cvt.rn.bf16x2.f32 %0, %1, %2;" : "=r"(lp) : "f"(rb), "f"(ra));
    h = hp; l = lp;
}
__device__ __forceinline__ void mma16816(float* c, const uint32_t* a, uint32_t b0, uint32_t b1) {
    asm volatile("mma.sync.aligned.m16n8k16.row.col.f32.bf16.bf16.f32 "
        "{%0,%1,%2,%3}, {%4,%5,%6,%7}, {%8,%9}, {%0,%1,%2,%3};"
        : "+f"(c[0]), "+f"(c[1]), "+f"(c[2]), "+f"(c[3])
        : "r"(a[0]), "r"(a[1]), "r"(a[2]), "r"(a[3]), "r"(b0), "r"(b1));
}
__device__ __forceinline__ void cpa16(uint32_t s, const void* g) {
    asm volatile("cp.async.cg.shared.global [%0], [%1], 16;" :: "r"(s), "l"(g));
}
#define CP_COMMIT() asm volatile("cp.async.commit_group;" ::: "memory")
#define CP_WAIT1()  asm volatile("cp.async.wait_group 1;" ::: "memory")
#define CP_WAIT0()  asm volatile("cp.async.wait_group 0;" ::: "memory")

__device__ __forceinline__ void prefetch_tile(uint32_t bufb, int tg, int tid) {
    const uint4* s1 = g_yc1 + tg * 2048;
    const uint4* s2 = g_yc2 + tg * 2048;
#pragma unroll
    for (int i = 0; i < 8; i++) {
        int idx = tid + 256 * i;
        cpa16(bufb + B_G1 + idx * 16, s1 + idx);
        cpa16(bufb + B_G2 + idx * 16, s2 + idx);
    }
    if (tid < 16) cpa16(bufb + B_Y2 + tid * 16, ((const uint4*)(g_y2 + tg * 64)) + tid);
}

// ---------------- precompute: fused split blobs + y2 (smem-staged) ----------------
__global__ void gmm_prep_kernel(const float* __restrict__ Y) {
    __shared__ float ys[BN * DDIM];       // 32KB tile of Y
    const int tile = blockIdx.x, tid = threadIdx.x;
    const float* src = Y + (size_t)tile * BN * DDIM;
#pragma unroll
    for (int i = 0; i < 8; i++) {
        int idx = tid + 256 * i;
        *reinterpret_cast<float4*>(ys + idx * 4) =
            *reinterpret_cast<const float4*>(src + idx * 4);
    }
    __syncthreads();

    // y2: 4 threads per key row
    {
        int row = tid >> 2, part = tid & 3;
        const float* r = ys + row * DDIM + part * 32;
        float s = 0.0f;
#pragma unroll
        for (int i = 0; i < 32; i += 4) {
            float4 v = *reinterpret_cast<const float4*>(r + i);
            s += v.x * v.x + v.y * v.y + v.z * v.z + v.w * v.w;
        }
        s += __shfl_xor_sync(0xffffffffu, s, 1);
        s += __shfl_xor_sync(0xffffffffu, s, 2);
        if (part == 0) g_y2[tile * BN + row] = s;
    }

    // GEMM1 blob: slot s -> (kc = s>>8, nf = (s>>5)&7, rs = (s>>2)&7, q = s&3)
#pragma unroll
    for (int j = 0; j < 8; j++) {
        int s = tid + 256 * j;
        int kc = s >> 8, nf = (s >> 5) & 7, rs = (s >> 2) & 7, q = s & 3;
        int n = nf * 8 + rs, kb = kc * 16 + q * 2;
        const float* row = ys + n * DDIM;
        uint32_t h0, l0, h1, l1;
        split2(row[kb], row[kb + 1], h0, l0);
        split2(row[kb + 8], row[kb + 9], h1, l1);
        g_yc1[tile * 2048 + s] = make_uint4(h0, h1, l0, l1);
    }
    // GEMM2 blob: slot s -> (kc2 = s>>9, nf2 = (s>>5)&15, rs = (s>>2)&7, q = s&3)
#pragma unroll
    for (int j = 0; j < 8; j++) {
        int s = tid + 256 * j;
        int kc2 = s >> 9, nf2 = (s >> 5) & 15, rs = (s >> 2) & 7, q = s & 3;
        int d = nf2 * 8 + rs, k = kc2 * 16 + q * 2;
        uint32_t h0, l0, h1, l1;
        split2(ys[k * DDIM + d], ys[(k + 1) * DDIM + d], h0, l0);
        split2(ys[(k + 8) * DDIM + d], ys[(k + 9) * DDIM + d], h1, l1);
        g_yc2[tile * 2048 + s] = make_uint4(h0, h1, l0, l1);
    }
}

// ---------------- main fused kernel ----------------
__global__ __launch_bounds__(256, 1)
void gmm_main_kernel(const float* __restrict__ X, const float* __restrict__ T) {
    extern __shared__ uint8_t sb[];
    __shared__ float sh_a2[BM], sh_b2[BM];

    const int tid = threadIdx.x, lane = tid & 31, wid = tid >> 5;
    const int rb = blockIdx.x >> 2, q = blockIdx.x & 3;
    const int r0 = rb * BM;
    const int rw = wid * 16;
    const int rsub = lane >> 2;
    const int lq = lane & 3;
    const uint32_t sb0 = smem_u32(sb);

    if (tid < BM) {
        float tv = T[r0 + tid];
        float lm = -0.25f * tv * tv * (BETA_MAX - BETA_MIN) - 0.5f * tv * BETA_MIN;
        float mean = expf(lm);
        float var = fmaxf(1.0f - expf(2.0f * lm), 1e-12f);
        float iv = 1.0f / var;
        sh_a2[tid] = mean * iv * LOG2E;
        sh_b2[tid] = -0.5f * mean * mean * iv * LOG2E;
    }
    // kick off prefetch of tile 0 ASAP
    prefetch_tile(sb0 + BUF0, q * NT, tid);
    CP_COMMIT();
    __syncthreads();

    // Build A = a2_r * x_r, fused hi/lo layout:
    // addr(row, kc, q) = row*512 + (kc ^ (row&7))*64 + q*16; words {h(k0,k1), h(k8,k9), l, l}
    {
        int row = tid >> 1, half = tid & 1;
        float a2 = sh_a2[row];
        const float* src = X + (size_t)(r0 + row) * DDIM;
        uint8_t* abase = sb + XS + row * 512;
#pragma unroll
        for (int kc = half * 4; kc < half * 4 + 4; kc++) {
#pragma unroll
            for (int qq = 0; qq < 4; qq++) {
                int d = kc * 16 + qq * 2;
                float2 v0 = *reinterpret_cast<const float2*>(src + d);
                float2 v1 = *reinterpret_cast<const float2*>(src + d + 8);
                uint32_t h0, l0, h1, l1;
                split2(a2 * v0.x, a2 * v0.y, h0, l0);
                split2(a2 * v1.x, a2 * v1.y, h1, l1);
                *reinterpret_cast<uint4*>(abase + ((kc ^ (row & 7)) * 64 + qq * 16)) =
                    make_uint4(h0, h1, l0, l1);
            }
        }
    }

    const float b2a = sh_b2[rw + rsub];
    const float b2b = sh_b2[rw + rsub + 8];

    float o[16][4];
#pragma unroll
    for (int i = 0; i < 16; i++)
#pragma unroll
        for (int j = 0; j < 4; j++) o[i][j] = 0.0f;
    float m_a = -CUDART_INF_F, m_b = -CUDART_INF_F, l_a = 0.0f, l_b = 0.0f;

    for (int kt = 0; kt < NT; kt++) {
        const int cur = kt & 1;
        const uint8_t* buf = sb + BUF0 + cur * BUFSTRIDE;

        if (kt + 1 < NT) {
            prefetch_tile(sb0 + BUF0 + (1 - cur) * BUFSTRIDE, q * NT + kt + 1, tid);
            CP_COMMIT();
            CP_WAIT1();
        } else {
            CP_WAIT0();
        }
        __syncthreads();

        // ---- GEMM1: S[16][64] per warp, 3-term bf16 split, K=128 ----
        float s[8][4];
#pragma unroll
        for (int i = 0; i < 8; i++)
#pragma unroll
            for (int j = 0; j < 4; j++) s[i][j] = 0.0f;

        const uint8_t* arow1 = sb + XS + (rw + rsub) * 512;
        const uint8_t* arow2 = arow1 + 8 * 512;
#pragma unroll 2
        for (int kc = 0; kc < 8; kc++) {
            uint32_t oA = (uint32_t)((kc ^ rsub) * 64 + lq * 16);
            uint4 ua = *reinterpret_cast<const uint4*>(arow1 + oA);
            uint4 ub = *reinterpret_cast<const uint4*>(arow2 + oA);
            uint32_t ah[4] = { ua.x, ub.x, ua.y, ub.y };
            uint32_t al[4] = { ua.z, ub.z, ua.w, ub.w };
            const uint8_t* bbase = buf + B_G1 + kc * 4096 + lane * 16;
#pragma unroll
            for (int nf = 0; nf < 8; nf++) {
                uint4 bb = *reinterpret_cast<const uint4*>(bbase + nf * 512);
                mma16816(s[nf], ah, bb.x, bb.y);
                mma16816(s[nf], ah, bb.z, bb.w);
                mma16816(s[nf], al, bb.x, bb.y);
            }
        }

        // ---- bias + row max ----
        const float* y2p = (const float*)(buf + B_Y2);
        float mxa = -CUDART_INF_F, mxb = -CUDART_INF_F;
#pragma unroll
        for (int f = 0; f < 8; f++) {
            float2 y2v = *reinterpret_cast<const float2*>(y2p + f * 8 + lq * 2);
            s[f][0] = fmaf(b2a, y2v.x, s[f][0]);
            s[f][1] = fmaf(b2a, y2v.y, s[f][1]);
            s[f][2] = fmaf(b2b, y2v.x, s[f][2]);
            s[f][3] = fmaf(b2b, y2v.y, s[f][3]);
            mxa = fmaxf(mxa, fmaxf(s[f][0], s[f][1]));
            mxb = fmaxf(mxb, fmaxf(s[f][2], s[f][3]));
        }
        mxa = fmaxf(mxa, __shfl_xor_sync(0xffffffffu, mxa, 1));
        mxa = fmaxf(mxa, __shfl_xor_sync(0xffffffffu, mxa, 2));
        mxb = fmaxf(mxb, __shfl_xor_sync(0xffffffffu, mxb, 1));
        mxb = fmaxf(mxb, __shfl_xor_sync(0xffffffffu, mxb, 2));
        float mna = fmaxf(m_a, mxa), mnb = fmaxf(m_b, mxb);

        // ---- rescale only when some row's max advanced (warp-uniform skip) ----
        bool upd = (mna > m_a) || (mnb > m_b);
        if (__any_sync(0xffffffffu, upd)) {
            float ala = ex2f(m_a - mna), alb = ex2f(m_b - mnb);
            l_a *= ala; l_b *= alb;
#pragma unroll
            for (int nf = 0; nf < 16; nf++) {
                o[nf][0] *= ala; o[nf][1] *= ala;
                o[nf][2] *= alb; o[nf][3] *= alb;
            }
            m_a = mna; m_b = mnb;
        }

        // ---- exp + split + row sum ----
        float suma = 0.0f, sumb = 0.0f;
        uint32_t ph[16], pl[16];
#pragma unroll
        for (int f = 0; f < 8; f++) {
            float p0 = ex2f(s[f][0] - m_a), p1 = ex2f(s[f][1] - m_a);
            float p2 = ex2f(s[f][2] - m_b), p3 = ex2f(s[f][3] - m_b);
            suma += p0 + p1; sumb += p2 + p3;
            split2(p0, p1, ph[2 * f], pl[2 * f]);
            split2(p2, p3, ph[2 * f + 1], pl[2 * f + 1]);
        }
        suma += __shfl_xor_sync(0xffffffffu, suma, 1);
        suma += __shfl_xor_sync(0xffffffffu, suma, 2);
        sumb += __shfl_xor_sync(0xffffffffu, sumb, 1);
        sumb += __shfl_xor_sync(0xffffffffu, sumb, 2);
        l_a += suma;
        l_b += sumb;

        // ---- GEMM2: O[16][128] += P @ Y^T, 3-term split, K=64 ----
#pragma unroll
        for (int kc2 = 0; kc2 < 4; kc2++) {
            uint32_t ah[4] = { ph[4 * kc2], ph[4 * kc2 + 1], ph[4 * kc2 + 2], ph[4 * kc2 + 3] };
            uint32_t al_[4] = { pl[4 * kc2], pl[4 * kc2 + 1], pl[4 * kc2 + 2], pl[4 * kc2 + 3] };
            const uint8_t* bbase = buf + B_G2 + kc2 * 8192 + lane * 16;
#pragma unroll
            for (int nf2 = 0; nf2 < 16; nf2++) {
                uint4 bb = *reinterpret_cast<const uint4*>(bbase + nf2 * 512);
                mma16816(o[nf2], ah, bb.x, bb.y);
                mma16816(o[nf2], ah, bb.z, bb.w);
                mma16816(o[nf2], al_, bb.x, bb.y);
            }
        }
        __syncthreads();   // all warps done with buf[cur] before next prefetch overwrites it
    }

    // ---- write split partials ----
    {
        int ga = r0 + rw + rsub;
        int gbrow = ga + 8;
        if (lq == 0) {
            g_pm[q * NROWS + ga] = m_a;  g_pl[q * NROWS + ga] = l_a;
            g_pm[q * NROWS + gbrow] = m_b; g_pl[q * NROWS + gbrow] = l_b;
        }
        float* da = g_pO + ((size_t)(q * NROWS + ga)) * DDIM + lq * 2;
        float* db = g_pO + ((size_t)(q * NROWS + gbrow)) * DDIM + lq * 2;
#pragma unroll
        for (int nf = 0; nf < 16; nf++) {
            *reinterpret_cast<float2*>(da + nf * 8) = make_float2(o[nf][0], o[nf][1]);
            *reinterpret_cast<float2*>(db + nf * 8) = make_float2(o[nf][2], o[nf][3]);
        }
    }
}

// ---------------- merge splits + epilogue ----------------
__global__ void gmm_merge_kernel(const float* __restrict__ X, const float* __restrict__ T,
                                 float* __restrict__ out) {
    int row = blockIdx.x * 2 + (threadIdx.x >> 7);
    int d = threadIdx.x & 127;
    float tv = T[row];
    float lm = -0.25f * tv * tv * (BETA_MAX - BETA_MIN) - 0.5f * tv * BETA_MIN;
    float var = fmaxf(1.0f - expf(2.0f * lm), 1e-12f);
    float iv = 1.0f / var;
    float M = -CUDART_INF_F;
#pragma unroll
    for (int s = 0; s < SPLITK; s++) M = fmaxf(M, g_pm[s * NROWS + row]);
    float L = 0.0f, O = 0.0f;
#pragma unroll
    for (int s = 0; s < SPLITK; s++) {
        float w = fexp2(g_pm[s * NROWS + row] - M);
        L += g_pl[s * NROWS + row] * w;
        O += g_pO[((size_t)(s * NROWS + row)) * DDIM + d] * w;
    }
    out[(size_t)row * DDIM + d] = (O / L - X[(size_t)row * DDIM + d]) * iv;
}

// ---------------------------------------------------------------------------
extern "C" void kernel_launch(void* const* d_in, const int* in_sizes, int n_in,
                              void* d_out, int out_size) {
    (void)n_in; (void)out_size;
    const float* x = (const float*)d_in[0];
    const float* t = (const float*)d_in[1];
    const float* y = (const float*)d_in[2];
    float* out = (float*)d_out;

    cudaFuncSetAttribute(gmm_main_kernel,
                         cudaFuncAttributeMaxDynamicSharedMemorySize, SMEM_BYTES);

    gmm_prep_kernel<<<TILES_ALL, 256>>>(y);
    gmm_main_kernel<<<(NROWS / BM) * SPLITK, 256, SMEM_BYTES>>>(x, t);
    gmm_merge_kernel<<<NROWS / 2, 256>>>(x, t, out);
}

// round 13
// speedup vs baseline: 1.5517x; 1.0144x over previous
#include <cuda_runtime.h>
#include <cuda_bf16.h>
#include <math_constants.h>
#include <cstdint>

#define BETA_MIN 0.1f
#define BETA_MAX 20.0f
#define LOG2E 1.4426950408889634f
#define DDIM 128
#define NROWS 4096
#define MKEYS 16384
#define SPLITK 4
#define BM 128
#define BN 64
#define NT 64            // key tiles per CTA (MKEYS/SPLITK/BN)
#define TILES_ALL 256

// smem layout
#define XS   0                 // A tile fused hi/lo: 128 rows * 512B = 64KB
#define BUF0 65536
#define BUFSTRIDE 66048        // 64KB blobs + 256B y2, 1KB aligned
#define B_G1 0                 // GEMM1 fused blob, 32KB
#define B_G2 32768             // GEMM2 fused blob, 32KB
#define B_Y2 65536
#define SMEM_BYTES (BUF0 + 2 * BUFSTRIDE)   // 197632

__device__ float g_y2[MKEYS];
__device__ uint4 g_yc1[TILES_ALL * 2048];   // fused GEMM1 B blobs (hi+lo interleaved)
__device__ uint4 g_yc2[TILES_ALL * 2048];   // fused GEMM2 B blobs
__device__ float g_pO[(size_t)SPLITK * NROWS * DDIM];
__device__ float g_pm[SPLITK * NROWS];
__device__ float g_pl[SPLITK * NROWS];

// ---------------- helpers ----------------
__device__ __forceinline__ uint32_t smem_u32(const void* p) {
    uint32_t a;
    asm("{ .reg .u64 t; cvta.to.shared.u64 t, %1; cvt.u32.u64 %0, t; }" : "=r"(a) : "l"(p));
    return a;
}
__device__ __forceinline__ float ex2f(float v) {
    float r;
    asm("ex2.approx.f32 %0, %1;" : "=f"(r) : "f"(v));
    return r;
}
// fast 2^v for v <= 0 (merge kernel only)
__device__ __forceinline__ float fexp2(float v) {
    v = fmaxf(v, -30.0f);
    float r = v + 12582912.0f;
    int   n = __float_as_int(r) - 0x4B400000;
    float f = v - (r - 12582912.0f);
    float p = 1.3333558146e-3f;
    p = fmaf(p, f, 9.6181291918e-3f);
    p = fmaf(p, f, 5.5504108664e-2f);
    p = fmaf(p, f, 2.4022650696e-1f);
    p = fmaf(p, f, 6.9314718056e-1f);
    p = fmaf(p, f, 1.0f);
    return __int_as_float(__float_as_int(p) + (n << 23));
}
// split (a,b) -> bf16x2 hi (low half = a) + bf16x2 lo residual
__device__ __forceinline__ void split2(float a, float b, uint32_t& h, uint32_t& l) {
    uint32_t hp, lp;
    asm("cvt.rn.bf16x2.f32 %0, %1, %2;" : "=r"(hp) : "f"(b), "f"(a));
    float ra = a - __int_as_float(hp << 16);
    float rb = b - __int_as_float(hp & 0xFFFF0000u);
    asm("cvt.rn.bf16x2.f32 %0, %1, %2;" : "=r"(lp) : "f"(rb), "f"(ra));
    h = hp; l = lp;
}
__device__ __forceinline__ void mma16816(float* c, const uint32_t* a, uint32_t b0, uint32_t b1) {
    asm volatile("mma.sync.aligned.m16n8k16.row.col.f32.bf16.bf16.f32 "
        "{%0,%1,%2,%3}, {%4,%5,%6,%7}, {%8,%9}, {%0,%1,%2,%3};"
        : "+f"(c[0]), "+f"(c[1]), "+f"(c[2]), "+f"(c[3])
        : "r"(a[0]), "r"(a[1]), "r"(a[2]), "r"(a[3]), "r"(b0), "r"(b1));
}
__device__ __forceinline__ void cpa16(uint32_t s, const void* g) {
    asm volatile("cp.async.cg.shared.global [%0], [%1], 16;" :: "r"(s), "l"(g));
}
#define CP_COMMIT() asm volatile("cp.async.commit_group;" ::: "memory")
#define CP_WAIT0()  asm volatile("cp.async.wait_group 0;" ::: "memory")

__device__ __forceinline__ void prefetch_tile(uint32_t bufb, int tg, int tid) {
    const uint4* s1 = g_yc1 + tg * 2048;
    const uint4* s2 = g_yc2 + tg * 2048;
#pragma unroll
    for (int i = 0; i < 8; i++) {
        int idx = tid + 256 * i;
        cpa16(bufb + B_G1 + idx * 16, s1 + idx);
        cpa16(bufb + B_G2 + idx * 16, s2 + idx);
    }
    if (tid < 16) cpa16(bufb + B_Y2 + tid * 16, ((const uint4*)(g_y2 + tg * 64)) + tid);
}

// ---------------- precompute: fused split blobs + y2 (smem-staged) ----------------
__global__ void gmm_prep_kernel(const float* __restrict__ Y) {
    __shared__ float ys[BN * DDIM];       // 32KB tile of Y
    const int tile = blockIdx.x, tid = threadIdx.x;
    const float* src = Y + (size_t)tile * BN * DDIM;
#pragma unroll
    for (int i = 0; i < 8; i++) {
        int idx = tid + 256 * i;
        *reinterpret_cast<float4*>(ys + idx * 4) =
            *reinterpret_cast<const float4*>(src + idx * 4);
    }
    __syncthreads();

    // y2: 4 threads per key row
    {
        int row = tid >> 2, part = tid & 3;
        const float* r = ys + row * DDIM + part * 32;
        float s = 0.0f;
#pragma unroll
        for (int i = 0; i < 32; i += 4) {
            float4 v = *reinterpret_cast<const float4*>(r + i);
            s += v.x * v.x + v.y * v.y + v.z * v.z + v.w * v.w;
        }
        s += __shfl_xor_sync(0xffffffffu, s, 1);
        s += __shfl_xor_sync(0xffffffffu, s, 2);
        if (part == 0) g_y2[tile * BN + row] = s;
    }

    // GEMM1 blob: slot s -> (kc = s>>8, nf = (s>>5)&7, rs = (s>>2)&7, q = s&3)
#pragma unroll
    for (int j = 0; j < 8; j++) {
        int s = tid + 256 * j;
        int kc = s >> 8, nf = (s >> 5) & 7, rs = (s >> 2) & 7, q = s & 3;
        int n = nf * 8 + rs, kb = kc * 16 + q * 2;
        const float* row = ys + n * DDIM;
        uint32_t h0, l0, h1, l1;
        split2(row[kb], row[kb + 1], h0, l0);
        split2(row[kb + 8], row[kb + 9], h1, l1);
        g_yc1[tile * 2048 + s] = make_uint4(h0, h1, l0, l1);
    }
    // GEMM2 blob: slot s -> (kc2 = s>>9, nf2 = (s>>5)&15, rs = (s>>2)&7, q = s&3)
#pragma unroll
    for (int j = 0; j < 8; j++) {
        int s = tid + 256 * j;
        int kc2 = s >> 9, nf2 = (s >> 5) & 15, rs = (s >> 2) & 7, q = s & 3;
        int d = nf2 * 8 + rs, k = kc2 * 16 + q * 2;
        uint32_t h0, l0, h1, l1;
        split2(ys[k * DDIM + d], ys[(k + 1) * DDIM + d], h0, l0);
        split2(ys[(k + 8) * DDIM + d], ys[(k + 9) * DDIM + d], h1, l1);
        g_yc2[tile * 2048 + s] = make_uint4(h0, h1, l0, l1);
    }
}

// ---------------- main fused kernel ----------------
__global__ __launch_bounds__(256, 1)
void gmm_main_kernel(const float* __restrict__ X, const float* __restrict__ T) {
    extern __shared__ uint8_t sb[];
    __shared__ float sh_a2[BM], sh_b2[BM];

    const int tid = threadIdx.x, lane = tid & 31, wid = tid >> 5;
    const int rb = blockIdx.x >> 2, q = blockIdx.x & 3;
    const int r0 = rb * BM;
    const int rw = wid * 16;
    const int rsub = lane >> 2;
    const int lq = lane & 3;
    const uint32_t sb0 = smem_u32(sb);

    if (tid < BM) {
        float tv = T[r0 + tid];
        float lm = -0.25f * tv * tv * (BETA_MAX - BETA_MIN) - 0.5f * tv * BETA_MIN;
        float mean = expf(lm);
        float var = fmaxf(1.0f - expf(2.0f * lm), 1e-12f);
        float iv = 1.0f / var;
        sh_a2[tid] = mean * iv * LOG2E;
        sh_b2[tid] = -0.5f * mean * mean * iv * LOG2E;
    }
    // kick off prefetch of tile 0 ASAP
    prefetch_tile(sb0 + BUF0, q * NT, tid);
    CP_COMMIT();
    __syncthreads();

    // Build A = a2_r * x_r, fused hi/lo layout:
    // addr(row, kc, q) = row*512 + (kc ^ (row&7))*64 + q*16; words {h(k0,k1), h(k8,k9), l, l}
    {
        int row = tid >> 1, half = tid & 1;
        float a2 = sh_a2[row];
        const float* src = X + (size_t)(r0 + row) * DDIM;
        uint8_t* abase = sb + XS + row * 512;
#pragma unroll
        for (int kc = half * 4; kc < half * 4 + 4; kc++) {
#pragma unroll
            for (int qq = 0; qq < 4; qq++) {
                int d = kc * 16 + qq * 2;
                float2 v0 = *reinterpret_cast<const float2*>(src + d);
                float2 v1 = *reinterpret_cast<const float2*>(src + d + 8);
                uint32_t h0, l0, h1, l1;
                split2(a2 * v0.x, a2 * v0.y, h0, l0);
                split2(a2 * v1.x, a2 * v1.y, h1, l1);
                *reinterpret_cast<uint4*>(abase + ((kc ^ (row & 7)) * 64 + qq * 16)) =
                    make_uint4(h0, h1, l0, l1);
            }
        }
    }

    const float b2a = sh_b2[rw + rsub];
    const float b2b = sh_b2[rw + rsub + 8];
    const uint8_t* arow1 = sb + XS + (rw + rsub) * 512;
    const uint8_t* arow2 = arow1 + 8 * 512;

    float o[16][4];
#pragma unroll
    for (int i = 0; i < 16; i++)
#pragma unroll
        for (int j = 0; j < 4; j++) o[i][j] = 0.0f;
    float m_a = -CUDART_INF_F, m_b = -CUDART_INF_F, l_a = 0.0f, l_b = 0.0f;

    for (int kt = 0; kt < NT; kt++) {
        const uint8_t* buf = sb + BUF0 + (kt & 1) * BUFSTRIDE;

        // single barrier per tile:
        //  - each thread drains its own cp groups (tile kt data it copied)
        //  - barrier makes all copies visible AND confirms every warp finished
        //    reading buf[kt-1] (the target of the upcoming prefetch)
        CP_WAIT0();
        __syncthreads();
        if (kt + 1 < NT) {
            prefetch_tile(sb0 + BUF0 + ((kt + 1) & 1) * BUFSTRIDE, q * NT + kt + 1, tid);
            CP_COMMIT();
        }

        // ---- GEMM1: S[16][64] per warp, 3-term bf16 split, K=128 ----
        float s[8][4];
#pragma unroll
        for (int i = 0; i < 8; i++)
#pragma unroll
            for (int j = 0; j < 4; j++) s[i][j] = 0.0f;

#pragma unroll 2
        for (int kc = 0; kc < 8; kc++) {
            uint32_t oA = (uint32_t)((kc ^ rsub) * 64 + lq * 16);
            uint4 ua = *reinterpret_cast<const uint4*>(arow1 + oA);
            uint4 ub = *reinterpret_cast<const uint4*>(arow2 + oA);
            uint32_t ah[4] = { ua.x, ub.x, ua.y, ub.y };
            uint32_t al[4] = { ua.z, ub.z, ua.w, ub.w };
            const uint8_t* bbase = buf + B_G1 + kc * 4096 + lane * 16;
#pragma unroll
            for (int nf = 0; nf < 8; nf++) {
                uint4 bb = *reinterpret_cast<const uint4*>(bbase + nf * 512);
                mma16816(s[nf], ah, bb.x, bb.y);
                mma16816(s[nf], ah, bb.z, bb.w);
                mma16816(s[nf], al, bb.x, bb.y);
            }
        }

        // ---- bias + row max ----
        const float* y2p = (const float*)(buf + B_Y2);
        float mxa = -CUDART_INF_F, mxb = -CUDART_INF_F;
#pragma unroll
        for (int f = 0; f < 8; f++) {
            float2 y2v = *reinterpret_cast<const float2*>(y2p + f * 8 + lq * 2);
            s[f][0] = fmaf(b2a, y2v.x, s[f][0]);
            s[f][1] = fmaf(b2a, y2v.y, s[f][1]);
            s[f][2] = fmaf(b2b, y2v.x, s[f][2]);
            s[f][3] = fmaf(b2b, y2v.y, s[f][3]);
            mxa = fmaxf(mxa, fmaxf(s[f][0], s[f][1]));
            mxb = fmaxf(mxb, fmaxf(s[f][2], s[f][3]));
        }
        mxa = fmaxf(mxa, __shfl_xor_sync(0xffffffffu, mxa, 1));
        mxa = fmaxf(mxa, __shfl_xor_sync(0xffffffffu, mxa, 2));
        mxb = fmaxf(mxb, __shfl_xor_sync(0xffffffffu, mxb, 1));
        mxb = fmaxf(mxb, __shfl_xor_sync(0xffffffffu, mxb, 2));
        float mna = fmaxf(m_a, mxa), mnb = fmaxf(m_b, mxb);

        // ---- rescale only when some row's max advanced (warp-uniform skip) ----
        bool upd = (mna > m_a) || (mnb > m_b);
        if (__any_sync(0xffffffffu, upd)) {
            float ala = ex2f(m_a - mna), alb = ex2f(m_b - mnb);
            l_a *= ala; l_b *= alb;
#pragma unroll
            for (int nf = 0; nf < 16; nf++) {
                o[nf][0] *= ala; o[nf][1] *= ala;
                o[nf][2] *= alb; o[nf][3] *= alb;
            }
            m_a = mna; m_b = mnb;
        }

        // ---- exp + split interleaved with GEMM2 (K=64, 3-term split) ----
        float suma = 0.0f, sumb = 0.0f;
        uint32_t ph[16], pl[16];
        const uint8_t* bbase2 = buf + B_G2 + lane * 16;
#pragma unroll
        for (int f = 0; f < 4; f++) {          // splits for kc2 0..1
            float p0 = ex2f(s[f][0] - m_a), p1 = ex2f(s[f][1] - m_a);
            float p2 = ex2f(s[f][2] - m_b), p3 = ex2f(s[f][3] - m_b);
            suma += p0 + p1; sumb += p2 + p3;
            split2(p0, p1, ph[2 * f], pl[2 * f]);
            split2(p2, p3, ph[2 * f + 1], pl[2 * f + 1]);
        }
        {   // GEMM2 kc2 = 0
            uint32_t ah[4] = { ph[0], ph[1], ph[2], ph[3] };
            uint32_t al_[4] = { pl[0], pl[1], pl[2], pl[3] };
#pragma unroll
            for (int nf2 = 0; nf2 < 16; nf2++) {
                uint4 bb = *reinterpret_cast<const uint4*>(bbase2 + nf2 * 512);
                mma16816(o[nf2], ah, bb.x, bb.y);
                mma16816(o[nf2], ah, bb.z, bb.w);
                mma16816(o[nf2], al_, bb.x, bb.y);
            }
        }
#pragma unroll
        for (int f = 4; f < 8; f++) {          // splits for kc2 2..3
            float p0 = ex2f(s[f][0] - m_a), p1 = ex2f(s[f][1] - m_a);
            float p2 = ex2f(s[f][2] - m_b), p3 = ex2f(s[f][3] - m_b);
            suma += p0 + p1; sumb += p2 + p3;
            split2(p0, p1, ph[2 * f], pl[2 * f]);
            split2(p2, p3, ph[2 * f + 1], pl[2 * f + 1]);
        }
#pragma unroll
        for (int kc2 = 1; kc2 < 4; kc2++) {
            uint32_t ah[4] = { ph[4 * kc2], ph[4 * kc2 + 1], ph[4 * kc2 + 2], ph[4 * kc2 + 3] };
            uint32_t al_[4] = { pl[4 * kc2], pl[4 * kc2 + 1], pl[4 * kc2 + 2], pl[4 * kc2 + 3] };
            const uint8_t* bk = bbase2 + kc2 * 8192;
#pragma unroll
            for (int nf2 = 0; nf2 < 16; nf2++) {
                uint4 bb = *reinterpret_cast<const uint4*>(bk + nf2 * 512);
                mma16816(o[nf2], ah, bb.x, bb.y);
                mma16816(o[nf2], ah, bb.z, bb.w);
                mma16816(o[nf2], al_, bb.x, bb.y);
            }
        }

        // ---- deferred l reduction (off the GEMM2 critical path) ----
        suma += __shfl_xor_sync(0xffffffffu, suma, 1);
        suma += __shfl_xor_sync(0xffffffffu, suma, 2);
        sumb += __shfl_xor_sync(0xffffffffu, sumb, 1);
        sumb += __shfl_xor_sync(0xffffffffu, sumb, 2);
        l_a += suma;
        l_b += sumb;
    }

    // ---- write split partials ----
    {
        int ga = r0 + rw + rsub;
        int gbrow = ga + 8;
        if (lq == 0) {
            g_pm[q * NROWS + ga] = m_a;  g_pl[q * NROWS + ga] = l_a;
            g_pm[q * NROWS + gbrow] = m_b; g_pl[q * NROWS + gbrow] = l_b;
        }
        float* da = g_pO + ((size_t)(q * NROWS + ga)) * DDIM + lq * 2;
        float* db = g_pO + ((size_t)(q * NROWS + gbrow)) * DDIM + lq * 2;
#pragma unroll
        for (int nf = 0; nf < 16; nf++) {
            *reinterpret_cast<float2*>(da + nf * 8) = make_float2(o[nf][0], o[nf][1]);
            *reinterpret_cast<float2*>(db + nf * 8) = make_float2(o[nf][2], o[nf][3]);
        }
    }
}

// ---------------- merge splits + epilogue ----------------
__global__ void gmm_merge_kernel(const float* __restrict__ X, const float* __restrict__ T,
                                 float* __restrict__ out) {
    int row = blockIdx.x * 2 + (threadIdx.x >> 7);
    int d = threadIdx.x & 127;
    float tv = T[row];
    float lm = -0.25f * tv * tv * (BETA_MAX - BETA_MIN) - 0.5f * tv * BETA_MIN;
    float var = fmaxf(1.0f - expf(2.0f * lm), 1e-12f);
    float iv = 1.0f / var;
    float M = -CUDART_INF_F;
#pragma unroll
    for (int s = 0; s < SPLITK; s++) M = fmaxf(M, g_pm[s * NROWS + row]);
    float L = 0.0f, O = 0.0f;
#pragma unroll
    for (int s = 0; s < SPLITK; s++) {
        float w = fexp2(g_pm[s * NROWS + row] - M);
        L += g_pl[s * NROWS + row] * w;
        O += g_pO[((size_t)(s * NROWS + row)) * DDIM + d] * w;
    }
    out[(size_t)row * DDIM + d] = (O / L - X[(size_t)row * DDIM + d]) * iv;
}

// ---------------------------------------------------------------------------
extern "C" void kernel_launch(void* const* d_in, const int* in_sizes, int n_in,
                              void* d_out, int out_size) {
    (void)n_in; (void)out_size;
    const float* x = (const float*)d_in[0];
    const float* t = (const float*)d_in[1];
    const float* y = (const float*)d_in[2];
    float* out = (float*)d_out;

    cudaFuncSetAttribute(gmm_main_kernel,
                         cudaFuncAttributeMaxDynamicSharedMemorySize, SMEM_BYTES);

    gmm_prep_kernel<<<TILES_ALL, 256>>>(y);
    gmm_main_kernel<<<(NROWS / BM) * SPLITK, 256, SMEM_BYTES>>>(x, t);
    gmm_merge_kernel<<<NROWS / 2, 256>>>(x, t, out);
}

// round 14
// speedup vs baseline: 1.6853x; 1.0861x over previous
#include <cuda_runtime.h>
#include <cuda_bf16.h>
#include <math_constants.h>
#include <cstdint>

#define BETA_MIN 0.1f
#define BETA_MAX 20.0f
#define LOG2E 1.4426950408889634f
#define DDIM 128
#define NROWS 4096
#define MKEYS 16384
#define BM 128
#define BN 64
#define TILES_ALL 256
#define NCTA 148
#define NUNITS 1024          // 32 rowblocks x 32 chunks (8 tiles each)
#define NSLOT 8              // partial slots per rowblock

// smem layout
#define XS   0                 // A tile fused hi/lo: 128 rows * 512B = 64KB
#define BUF0 65536
#define BUFSTRIDE 66048        // 64KB blobs + 256B y2, 1KB aligned
#define B_G1 0                 // GEMM1 fused blob, 32KB
#define B_G2 32768             // GEMM2 fused blob, 32KB
#define B_Y2 65536
#define SMEM_BYTES (BUF0 + 2 * BUFSTRIDE)   // 197632

__device__ float g_y2[MKEYS];
__device__ uint4 g_yc1[TILES_ALL * 2048];   // fused GEMM1 B blobs (hi+lo interleaved)
__device__ uint4 g_yc2[TILES_ALL * 2048];   // fused GEMM2 B blobs
__device__ float g_pO[(size_t)NSLOT * NROWS * DDIM];
__device__ float g_pm[NSLOT * NROWS];
__device__ float g_pl[NSLOT * NROWS];

// ---------------- helpers ----------------
__device__ __forceinline__ uint32_t smem_u32(const void* p) {
    uint32_t a;
    asm("{ .reg .u64 t; cvta.to.shared.u64 t, %1; cvt.u32.u64 %0, t; }" : "=r"(a) : "l"(p));
    return a;
}
__device__ __forceinline__ float ex2f(float v) {
    float r;
    asm("ex2.approx.f32 %0, %1;" : "=f"(r) : "f"(v));
    return r;
}
// fast 2^v for v <= 0 (merge kernel only)
__device__ __forceinline__ float fexp2(float v) {
    v = fmaxf(v, -30.0f);
    float r = v + 12582912.0f;
    int   n = __float_as_int(r) - 0x4B400000;
    float f = v - (r - 12582912.0f);
    float p = 1.3333558146e-3f;
    p = fmaf(p, f, 9.6181291918e-3f);
    p = fmaf(p, f, 5.5504108664e-2f);
    p = fmaf(p, f, 2.4022650696e-1f);
    p = fmaf(p, f, 6.9314718056e-1f);
    p = fmaf(p, f, 1.0f);
    return __int_as_float(__float_as_int(p) + (n << 23));
}
// split (a,b) -> bf16x2 hi (low half = a) + bf16x2 lo residual
__device__ __forceinline__ void split2(float a, float b, uint32_t& h, uint32_t& l) {
    uint32_t hp, lp;
    asm("cvt.rn.bf16x2.f32 %0, %1, %2;" : "=r"(hp) : "f"(b), "f"(a));
    float ra = a - __int_as_float(hp << 16);
    float rb = b - __int_as_float(hp & 0xFFFF0000u);
    asm("cvt.rn.bf16x2.f32 %0, %1, %2;" : "=r"(lp) : "f"(rb), "f"(ra));
    h = hp; l = lp;
}
__device__ __forceinline__ void mma16816(float* c, const uint32_t* a, uint32_t b0, uint32_t b1) {
    asm volatile("mma.sync.aligned.m16n8k16.row.col.f32.bf16.bf16.f32 "
        "{%0,%1,%2,%3}, {%4,%5,%6,%7}, {%8,%9}, {%0,%1,%2,%3};"
        : "+f"(c[0]), "+f"(c[1]), "+f"(c[2]), "+f"(c[3])
        : "r"(a[0]), "r"(a[1]), "r"(a[2]), "r"(a[3]), "r"(b0), "r"(b1));
}
__device__ __forceinline__ void cpa16(uint32_t s, const void* g) {
    asm volatile("cp.async.cg.shared.global [%0], [%1], 16;" :: "r"(s), "l"(g));
}
#define CP_COMMIT() asm volatile("cp.async.commit_group;" ::: "memory")
#define CP_WAIT0()  asm volatile("cp.async.wait_group 0;" ::: "memory")

__device__ __forceinline__ void prefetch_tile(uint32_t bufb, int tg, int tid) {
    const uint4* s1 = g_yc1 + tg * 2048;
    const uint4* s2 = g_yc2 + tg * 2048;
#pragma unroll
    for (int i = 0; i < 8; i++) {
        int idx = tid + 256 * i;
        cpa16(bufb + B_G1 + idx * 16, s1 + idx);
        cpa16(bufb + B_G2 + idx * 16, s2 + idx);
    }
    if (tid < 16) cpa16(bufb + B_Y2 + tid * 16, ((const uint4*)(g_y2 + tg * 64)) + tid);
}

// unit range owned by CTA b: [ustart(b), ustart(b+1))
__device__ __forceinline__ int ustart(int b) { return (b * NUNITS) / NCTA; }

// ---------------- init: reset partial maxima ----------------
__global__ void gmm_init_kernel() {
    int i = (blockIdx.x * 256 + threadIdx.x) * 4;
    *reinterpret_cast<float4*>(g_pm + i) =
        make_float4(-CUDART_INF_F, -CUDART_INF_F, -CUDART_INF_F, -CUDART_INF_F);
}

// ---------------- precompute: fused split blobs + y2 (smem-staged) ----------------
__global__ void gmm_prep_kernel(const float* __restrict__ Y) {
    __shared__ float ys[BN * DDIM];       // 32KB tile of Y
    const int tile = blockIdx.x, tid = threadIdx.x;
    const float* src = Y + (size_t)tile * BN * DDIM;
#pragma unroll
    for (int i = 0; i < 8; i++) {
        int idx = tid + 256 * i;
        *reinterpret_cast<float4*>(ys + idx * 4) =
            *reinterpret_cast<const float4*>(src + idx * 4);
    }
    __syncthreads();

    // y2: 4 threads per key row
    {
        int row = tid >> 2, part = tid & 3;
        const float* r = ys + row * DDIM + part * 32;
        float s = 0.0f;
#pragma unroll
        for (int i = 0; i < 32; i += 4) {
            float4 v = *reinterpret_cast<const float4*>(r + i);
            s += v.x * v.x + v.y * v.y + v.z * v.z + v.w * v.w;
        }
        s += __shfl_xor_sync(0xffffffffu, s, 1);
        s += __shfl_xor_sync(0xffffffffu, s, 2);
        if (part == 0) g_y2[tile * BN + row] = s;
    }

    // GEMM1 blob
#pragma unroll
    for (int j = 0; j < 8; j++) {
        int s = tid + 256 * j;
        int kc = s >> 8, nf = (s >> 5) & 7, rs = (s >> 2) & 7, q = s & 3;
        int n = nf * 8 + rs, kb = kc * 16 + q * 2;
        const float* row = ys + n * DDIM;
        uint32_t h0, l0, h1, l1;
        split2(row[kb], row[kb + 1], h0, l0);
        split2(row[kb + 8], row[kb + 9], h1, l1);
        g_yc1[tile * 2048 + s] = make_uint4(h0, h1, l0, l1);
    }
    // GEMM2 blob
#pragma unroll
    for (int j = 0; j < 8; j++) {
        int s = tid + 256 * j;
        int kc2 = s >> 9, nf2 = (s >> 5) & 15, rs = (s >> 2) & 7, q = s & 3;
        int d = nf2 * 8 + rs, k = kc2 * 16 + q * 2;
        uint32_t h0, l0, h1, l1;
        split2(ys[k * DDIM + d], ys[(k + 1) * DDIM + d], h0, l0);
        split2(ys[(k + 8) * DDIM + d], ys[(k + 9) * DDIM + d], h1, l1);
        g_yc2[tile * 2048 + s] = make_uint4(h0, h1, l0, l1);
    }
}

// ---------------- main fused kernel (persistent work ranges) ----------------
__global__ __launch_bounds__(256, 1)
void gmm_main_kernel(const float* __restrict__ X, const float* __restrict__ T) {
    extern __shared__ uint8_t sb[];
    __shared__ float sh_a2[BM], sh_b2[BM];

    const int tid = threadIdx.x, lane = tid & 31, wid = tid >> 5;
    const int rw = wid * 16;
    const int rsub = lane >> 2;
    const int lq = lane & 3;
    const uint32_t sb0 = smem_u32(sb);
    const int b = blockIdx.x;
    const int u0 = ustart(b), u1 = ustart(b + 1);

    int u = u0;
    while (u < u1) {
        const int rb = u >> 5;                  // 32 units per rowblock
        const int ue = min(u1, (rb + 1) * 32);
        const int t0 = (u - (rb << 5)) * 8;     // first key tile of this segment
        const int t1 = (ue - (rb << 5)) * 8;    // end key tile
        const int r0 = rb * BM;

        // slot = b - b_first(rb)
        int bf = (int)(((long long)(rb << 5) * NCTA) >> 10);
        while (ustart(bf + 1) <= (rb << 5)) bf++;
        while (ustart(bf) > (rb << 5)) bf--;
        const int slot = b - bf;

        __syncthreads();   // all warps done with previous segment (XS, bufs, sh_*)

        // prefetch first tile of segment ASAP
        prefetch_tile(sb0 + BUF0 + (t0 & 1) * BUFSTRIDE, t0, tid);
        CP_COMMIT();

        if (tid < BM) {
            float tv = T[r0 + tid];
            float lm = -0.25f * tv * tv * (BETA_MAX - BETA_MIN) - 0.5f * tv * BETA_MIN;
            float mean = expf(lm);
            float var = fmaxf(1.0f - expf(2.0f * lm), 1e-12f);
            float iv = 1.0f / var;
            sh_a2[tid] = mean * iv * LOG2E;
            sh_b2[tid] = -0.5f * mean * mean * iv * LOG2E;
        }
        __syncthreads();

        // Build A = a2_r * x_r, fused hi/lo layout
        {
            int row = tid >> 1, half = tid & 1;
            float a2 = sh_a2[row];
            const float* src = X + (size_t)(r0 + row) * DDIM;
            uint8_t* abase = sb + XS + row * 512;
#pragma unroll
            for (int kc = half * 4; kc < half * 4 + 4; kc++) {
#pragma unroll
                for (int qq = 0; qq < 4; qq++) {
                    int d = kc * 16 + qq * 2;
                    float2 v0 = *reinterpret_cast<const float2*>(src + d);
                    float2 v1 = *reinterpret_cast<const float2*>(src + d + 8);
                    uint32_t h0, l0, h1, l1;
                    split2(a2 * v0.x, a2 * v0.y, h0, l0);
                    split2(a2 * v1.x, a2 * v1.y, h1, l1);
                    *reinterpret_cast<uint4*>(abase + ((kc ^ (row & 7)) * 64 + qq * 16)) =
                        make_uint4(h0, h1, l0, l1);
                }
            }
        }

        const float b2a = sh_b2[rw + rsub];
        const float b2b = sh_b2[rw + rsub + 8];
        const uint8_t* arow1 = sb + XS + (rw + rsub) * 512;
        const uint8_t* arow2 = arow1 + 8 * 512;

        float o[16][4];
#pragma unroll
        for (int i = 0; i < 16; i++)
#pragma unroll
            for (int j = 0; j < 4; j++) o[i][j] = 0.0f;
        float m_a = -CUDART_INF_F, m_b = -CUDART_INF_F, l_a = 0.0f, l_b = 0.0f;

        for (int kt = t0; kt < t1; kt++) {
            const uint8_t* buf = sb + BUF0 + (kt & 1) * BUFSTRIDE;

            CP_WAIT0();
            __syncthreads();   // tile data visible; buf[kt-1] free for prefetch
            if (kt + 1 < t1) {
                prefetch_tile(sb0 + BUF0 + ((kt + 1) & 1) * BUFSTRIDE, kt + 1, tid);
                CP_COMMIT();
            }

            // ---- GEMM1: S[16][64] per warp, 3-term bf16 split, K=128 ----
            float s[8][4];
#pragma unroll
            for (int i = 0; i < 8; i++)
#pragma unroll
                for (int j = 0; j < 4; j++) s[i][j] = 0.0f;

#pragma unroll 2
            for (int kc = 0; kc < 8; kc++) {
                uint32_t oA = (uint32_t)((kc ^ rsub) * 64 + lq * 16);
                uint4 ua = *reinterpret_cast<const uint4*>(arow1 + oA);
                uint4 ub = *reinterpret_cast<const uint4*>(arow2 + oA);
                uint32_t ah[4] = { ua.x, ub.x, ua.y, ub.y };
                uint32_t al[4] = { ua.z, ub.z, ua.w, ub.w };
                const uint8_t* bbase = buf + B_G1 + kc * 4096 + lane * 16;
#pragma unroll
                for (int nf = 0; nf < 8; nf++) {
                    uint4 bb = *reinterpret_cast<const uint4*>(bbase + nf * 512);
                    mma16816(s[nf], ah, bb.x, bb.y);
                    mma16816(s[nf], ah, bb.z, bb.w);
                    mma16816(s[nf], al, bb.x, bb.y);
                }
            }

            // ---- bias + row max ----
            const float* y2p = (const float*)(buf + B_Y2);
            float mxa = -CUDART_INF_F, mxb = -CUDART_INF_F;
#pragma unroll
            for (int f = 0; f < 8; f++) {
                float2 y2v = *reinterpret_cast<const float2*>(y2p + f * 8 + lq * 2);
                s[f][0] = fmaf(b2a, y2v.x, s[f][0]);
                s[f][1] = fmaf(b2a, y2v.y, s[f][1]);
                s[f][2] = fmaf(b2b, y2v.x, s[f][2]);
                s[f][3] = fmaf(b2b, y2v.y, s[f][3]);
                mxa = fmaxf(mxa, fmaxf(s[f][0], s[f][1]));
                mxb = fmaxf(mxb, fmaxf(s[f][2], s[f][3]));
            }
            mxa = fmaxf(mxa, __shfl_xor_sync(0xffffffffu, mxa, 1));
            mxa = fmaxf(mxa, __shfl_xor_sync(0xffffffffu, mxa, 2));
            mxb = fmaxf(mxb, __shfl_xor_sync(0xffffffffu, mxb, 1));
            mxb = fmaxf(mxb, __shfl_xor_sync(0xffffffffu, mxb, 2));
            float mna = fmaxf(m_a, mxa), mnb = fmaxf(m_b, mxb);

            // ---- rescale only when some row's max advanced ----
            bool upd = (mna > m_a) || (mnb > m_b);
            if (__any_sync(0xffffffffu, upd)) {
                float ala = ex2f(m_a - mna), alb = ex2f(m_b - mnb);
                l_a *= ala; l_b *= alb;
#pragma unroll
                for (int nf = 0; nf < 16; nf++) {
                    o[nf][0] *= ala; o[nf][1] *= ala;
                    o[nf][2] *= alb; o[nf][3] *= alb;
                }
                m_a = mna; m_b = mnb;
            }

            // ---- exp + split interleaved with GEMM2 ----
            float suma = 0.0f, sumb = 0.0f;
            uint32_t ph[16], pl[16];
            const uint8_t* bbase2 = buf + B_G2 + lane * 16;
#pragma unroll
            for (int f = 0; f < 4; f++) {
                float p0 = ex2f(s[f][0] - m_a), p1 = ex2f(s[f][1] - m_a);
                float p2 = ex2f(s[f][2] - m_b), p3 = ex2f(s[f][3] - m_b);
                suma += p0 + p1; sumb += p2 + p3;
                split2(p0, p1, ph[2 * f], pl[2 * f]);
                split2(p2, p3, ph[2 * f + 1], pl[2 * f + 1]);
            }
            {   // GEMM2 kc2 = 0
                uint32_t ah[4] = { ph[0], ph[1], ph[2], ph[3] };
                uint32_t al_[4] = { pl[0], pl[1], pl[2], pl[3] };
#pragma unroll
                for (int nf2 = 0; nf2 < 16; nf2++) {
                    uint4 bb = *reinterpret_cast<const uint4*>(bbase2 + nf2 * 512);
                    mma16816(o[nf2], ah, bb.x, bb.y);
                    mma16816(o[nf2], ah, bb.z, bb.w);
                    mma16816(o[nf2], al_, bb.x, bb.y);
                }
            }
#pragma unroll
            for (int f = 4; f < 8; f++) {
                float p0 = ex2f(s[f][0] - m_a), p1 = ex2f(s[f][1] - m_a);
                float p2 = ex2f(s[f][2] - m_b), p3 = ex2f(s[f][3] - m_b);
                suma += p0 + p1; sumb += p2 + p3;
                split2(p0, p1, ph[2 * f], pl[2 * f]);
                split2(p2, p3, ph[2 * f + 1], pl[2 * f + 1]);
            }
#pragma unroll
            for (int kc2 = 1; kc2 < 4; kc2++) {
                uint32_t ah[4] = { ph[4 * kc2], ph[4 * kc2 + 1], ph[4 * kc2 + 2], ph[4 * kc2 + 3] };
                uint32_t al_[4] = { pl[4 * kc2], pl[4 * kc2 + 1], pl[4 * kc2 + 2], pl[4 * kc2 + 3] };
                const uint8_t* bk = bbase2 + kc2 * 8192;
#pragma unroll
                for (int nf2 = 0; nf2 < 16; nf2++) {
                    uint4 bb = *reinterpret_cast<const uint4*>(bk + nf2 * 512);
                    mma16816(o[nf2], ah, bb.x, bb.y);
                    mma16816(o[nf2], ah, bb.z, bb.w);
                    mma16816(o[nf2], al_, bb.x, bb.y);
                }
            }

            suma += __shfl_xor_sync(0xffffffffu, suma, 1);
            suma += __shfl_xor_sync(0xffffffffu, suma, 2);
            sumb += __shfl_xor_sync(0xffffffffu, sumb, 1);
            sumb += __shfl_xor_sync(0xffffffffu, sumb, 2);
            l_a += suma;
            l_b += sumb;
        }

        // ---- write segment partials into this rowblock's slot ----
        {
            int ga = r0 + rw + rsub;
            int gbrow = ga + 8;
            if (lq == 0) {
                g_pm[slot * NROWS + ga] = m_a;   g_pl[slot * NROWS + ga] = l_a;
                g_pm[slot * NROWS + gbrow] = m_b; g_pl[slot * NROWS + gbrow] = l_b;
            }
            float* da = g_pO + ((size_t)(slot * NROWS + ga)) * DDIM + lq * 2;
            float* db = g_pO + ((size_t)(slot * NROWS + gbrow)) * DDIM + lq * 2;
#pragma unroll
            for (int nf = 0; nf < 16; nf++) {
                *reinterpret_cast<float2*>(da + nf * 8) = make_float2(o[nf][0], o[nf][1]);
                *reinterpret_cast<float2*>(db + nf * 8) = make_float2(o[nf][2], o[nf][3]);
            }
        }

        u = ue;
    }
}

// ---------------- merge slots + epilogue ----------------
__global__ void gmm_merge_kernel(const float* __restrict__ X, const float* __restrict__ T,
                                 float* __restrict__ out) {
    int row = blockIdx.x * 2 + (threadIdx.x >> 7);
    int d = threadIdx.x & 127;
    float tv = T[row];
    float lm = -0.25f * tv * tv * (BETA_MAX - BETA_MIN) - 0.5f * tv * BETA_MIN;
    float var = fmaxf(1.0f - expf(2.0f * lm), 1e-12f);
    float iv = 1.0f / var;
    float M = -CUDART_INF_F;
    float pm[NSLOT];
#pragma unroll
    for (int s = 0; s < NSLOT; s++) {
        pm[s] = g_pm[s * NROWS + row];
        M = fmaxf(M, pm[s]);
    }
    float L = 0.0f, O = 0.0f;
#pragma unroll
    for (int s = 0; s < NSLOT; s++) {
        if (pm[s] > -1e30f) {
            float w = fexp2(pm[s] - M);
            L += g_pl[s * NROWS + row] * w;
            O += g_pO[((size_t)(s * NROWS + row)) * DDIM + d] * w;
        }
    }
    out[(size_t)row * DDIM + d] = (O / L - X[(size_t)row * DDIM + d]) * iv;
}

// ---------------------------------------------------------------------------
extern "C" void kernel_launch(void* const* d_in, const int* in_sizes, int n_in,
                              void* d_out, int out_size) {
    (void)n_in; (void)out_size;
    const float* x = (const float*)d_in[0];
    const float* t = (const float*)d_in[1];
    const float* y = (const float*)d_in[2];
    float* out = (float*)d_out;

    cudaFuncSetAttribute(gmm_main_kernel,
                         cudaFuncAttributeMaxDynamicSharedMemorySize, SMEM_BYTES);

    gmm_init_kernel<<<NSLOT * NROWS / 1024, 256>>>();
    gmm_prep_kernel<<<TILES_ALL, 256>>>(y);
    gmm_main_kernel<<<NCTA, 256, SMEM_BYTES>>>(x, t);
    gmm_merge_kernel<<<NROWS / 2, 256>>>(x, t, out);
}

// round 15
// speedup vs baseline: 1.6859x; 1.0003x over previous
#include <cuda_runtime.h>
#include <cuda_bf16.h>
#include <math_constants.h>
#include <cstdint>

#define BETA_MIN 0.1f
#define BETA_MAX 20.0f
#define LOG2E 1.4426950408889634f
#define DDIM 128
#define NROWS 4096
#define MKEYS 16384
#define BM 128
#define BN 64
#define TILES_ALL 256
#define NCTA 148
#define NUNITS 1024          // 32 rowblocks x 32 chunks (8 tiles each)
#define NSLOT 8              // partial slots per rowblock

// smem layout
#define XS   0                 // A tile fused hi/lo: 128 rows * 512B = 64KB
#define BUF0 65536
#define BUFSTRIDE 66048        // 64KB blobs + 256B y2, 1KB aligned
#define B_G1 0                 // GEMM1 fused blob, 32KB
#define B_G2 32768             // GEMM2 fused blob, 32KB
#define B_Y2 65536
#define SMEM_BYTES (BUF0 + 2 * BUFSTRIDE)   // 197632

#define YSTRIDE 132            // padded Y staging stride (floats) in prep

__device__ float g_y2[MKEYS];
__device__ uint4 g_yc1[TILES_ALL * 2048];   // fused GEMM1 B blobs (hi+lo interleaved)
__device__ uint4 g_yc2[TILES_ALL * 2048];   // fused GEMM2 B blobs
__device__ float g_pO[(size_t)NSLOT * NROWS * DDIM];
__device__ float g_pm[NSLOT * NROWS];
__device__ float g_pl[NSLOT * NROWS];

// ---------------- helpers ----------------
__device__ __forceinline__ uint32_t smem_u32(const void* p) {
    uint32_t a;
    asm("{ .reg .u64 t; cvta.to.shared.u64 t, %1; cvt.u32.u64 %0, t; }" : "=r"(a) : "l"(p));
    return a;
}
__device__ __forceinline__ float ex2f(float v) {
    float r;
    asm("ex2.approx.f32 %0, %1;" : "=f"(r) : "f"(v));
    return r;
}
// fast 2^v for v <= 0 (merge kernel only)
__device__ __forceinline__ float fexp2(float v) {
    v = fmaxf(v, -30.0f);
    float r = v + 12582912.0f;
    int   n = __float_as_int(r) - 0x4B400000;
    float f = v - (r - 12582912.0f);
    float p = 1.3333558146e-3f;
    p = fmaf(p, f, 9.6181291918e-3f);
    p = fmaf(p, f, 5.5504108664e-2f);
    p = fmaf(p, f, 2.4022650696e-1f);
    p = fmaf(p, f, 6.9314718056e-1f);
    p = fmaf(p, f, 1.0f);
    return __int_as_float(__float_as_int(p) + (n << 23));
}
// split (a,b) -> bf16x2 hi (low half = a) + bf16x2 lo residual
__device__ __forceinline__ void split2(float a, float b, uint32_t& h, uint32_t& l) {
    uint32_t hp, lp;
    asm("cvt.rn.bf16x2.f32 %0, %1, %2;" : "=r"(hp) : "f"(b), "f"(a));
    float ra = a - __int_as_float(hp << 16);
    float rb = b - __int_as_float(hp & 0xFFFF0000u);
    asm("cvt.rn.bf16x2.f32 %0, %1, %2;" : "=r"(lp) : "f"(rb), "f"(ra));
    h = hp; l = lp;
}
__device__ __forceinline__ void mma16816(float* c, const uint32_t* a, uint32_t b0, uint32_t b1) {
    asm volatile("mma.sync.aligned.m16n8k16.row.col.f32.bf16.bf16.f32 "
        "{%0,%1,%2,%3}, {%4,%5,%6,%7}, {%8,%9}, {%0,%1,%2,%3};"
        : "+f"(c[0]), "+f"(c[1]), "+f"(c[2]), "+f"(c[3])
        : "r"(a[0]), "r"(a[1]), "r"(a[2]), "r"(a[3]), "r"(b0), "r"(b1));
}
__device__ __forceinline__ void cpa16(uint32_t s, const void* g) {
    asm volatile("cp.async.cg.shared.global [%0], [%1], 16;" :: "r"(s), "l"(g));
}
#define CP_COMMIT() asm volatile("cp.async.commit_group;" ::: "memory")
#define CP_WAIT0()  asm volatile("cp.async.wait_group 0;" ::: "memory")

__device__ __forceinline__ void prefetch_tile(uint32_t bufb, int tg, int tid) {
    const uint4* s1 = g_yc1 + tg * 2048;
    const uint4* s2 = g_yc2 + tg * 2048;
#pragma unroll
    for (int i = 0; i < 8; i++) {
        int idx = tid + 256 * i;
        cpa16(bufb + B_G1 + idx * 16, s1 + idx);
        cpa16(bufb + B_G2 + idx * 16, s2 + idx);
    }
    if (tid < 16) cpa16(bufb + B_Y2 + tid * 16, ((const uint4*)(g_y2 + tg * 64)) + tid);
}

// unit range owned by CTA b: [ustart(b), ustart(b+1))
__device__ __forceinline__ int ustart(int b) { return (b * NUNITS) / NCTA; }

// ---------------- init: reset partial maxima ----------------
__global__ void gmm_init_kernel() {
    int i = (blockIdx.x * 256 + threadIdx.x) * 4;
    *reinterpret_cast<float4*>(g_pm + i) =
        make_float4(-CUDART_INF_F, -CUDART_INF_F, -CUDART_INF_F, -CUDART_INF_F);
}

// ---------------- precompute: fused split blobs + y2 (padded smem staging) ----------------
__global__ void gmm_prep_kernel(const float* __restrict__ Y) {
    __shared__ float ys[BN * YSTRIDE];    // padded: bank-conflict-free column gathers
    const int tile = blockIdx.x, tid = threadIdx.x;
    const float* src = Y + (size_t)tile * BN * DDIM;
#pragma unroll
    for (int i = 0; i < 8; i++) {
        int idx = tid + 256 * i;
        int row = idx >> 5;               // 32 float4 per row
        int col = (idx & 31) * 4;
        *reinterpret_cast<float4*>(ys + row * YSTRIDE + col) =
            *reinterpret_cast<const float4*>(src + row * DDIM + col);
    }
    __syncthreads();

    // y2: 4 threads per key row
    {
        int row = tid >> 2, part = tid & 3;
        const float* r = ys + row * YSTRIDE + part * 32;
        float s = 0.0f;
#pragma unroll
        for (int i = 0; i < 32; i += 4) {
            float4 v = *reinterpret_cast<const float4*>(r + i);
            s += v.x * v.x + v.y * v.y + v.z * v.z + v.w * v.w;
        }
        s += __shfl_xor_sync(0xffffffffu, s, 1);
        s += __shfl_xor_sync(0xffffffffu, s, 2);
        if (part == 0) g_y2[tile * BN + row] = s;
    }

    // GEMM1 blob
#pragma unroll
    for (int j = 0; j < 8; j++) {
        int s = tid + 256 * j;
        int kc = s >> 8, nf = (s >> 5) & 7, rs = (s >> 2) & 7, q = s & 3;
        int n = nf * 8 + rs, kb = kc * 16 + q * 2;
        const float* row = ys + n * YSTRIDE;
        uint32_t h0, l0, h1, l1;
        split2(row[kb], row[kb + 1], h0, l0);
        split2(row[kb + 8], row[kb + 9], h1, l1);
        g_yc1[tile * 2048 + s] = make_uint4(h0, h1, l0, l1);
    }
    // GEMM2 blob
#pragma unroll
    for (int j = 0; j < 8; j++) {
        int s = tid + 256 * j;
        int kc2 = s >> 9, nf2 = (s >> 5) & 15, rs = (s >> 2) & 7, q = s & 3;
        int d = nf2 * 8 + rs, k = kc2 * 16 + q * 2;
        uint32_t h0, l0, h1, l1;
        split2(ys[k * YSTRIDE + d], ys[(k + 1) * YSTRIDE + d], h0, l0);
        split2(ys[(k + 8) * YSTRIDE + d], ys[(k + 9) * YSTRIDE + d], h1, l1);
        g_yc2[tile * 2048 + s] = make_uint4(h0, h1, l0, l1);
    }
}

// ---------------- main fused kernel (persistent work ranges) ----------------
__global__ __launch_bounds__(256, 1)
void gmm_main_kernel(const float* __restrict__ X, const float* __restrict__ T) {
    extern __shared__ uint8_t sb[];
    __shared__ float sh_a2[BM], sh_b2[BM];

    const int tid = threadIdx.x, lane = tid & 31, wid = tid >> 5;
    const int rw = wid * 16;
    const int rsub = lane >> 2;
    const int lq = lane & 3;
    const uint32_t sb0 = smem_u32(sb);
    const int b = blockIdx.x;
    const int u0 = ustart(b), u1 = ustart(b + 1);

    int u = u0;
    while (u < u1) {
        const int rb = u >> 5;                  // 32 units per rowblock
        const int ue = min(u1, (rb + 1) * 32);
        const int t0 = (u - (rb << 5)) * 8;     // first key tile of this segment
        const int t1 = (ue - (rb << 5)) * 8;    // end key tile
        const int r0 = rb * BM;

        // slot = b - b_first(rb)
        int bf = (int)(((long long)(rb << 5) * NCTA) >> 10);
        while (ustart(bf + 1) <= (rb << 5)) bf++;
        while (ustart(bf) > (rb << 5)) bf--;
        const int slot = b - bf;

        __syncthreads();   // all warps done with previous segment (XS, bufs, sh_*)

        // prefetch first tile of segment ASAP
        prefetch_tile(sb0 + BUF0 + (t0 & 1) * BUFSTRIDE, t0, tid);
        CP_COMMIT();

        if (tid < BM) {
            float tv = T[r0 + tid];
            float lm = -0.25f * tv * tv * (BETA_MAX - BETA_MIN) - 0.5f * tv * BETA_MIN;
            float mean = expf(lm);
            float var = fmaxf(1.0f - expf(2.0f * lm), 1e-12f);
            float iv = 1.0f / var;
            sh_a2[tid] = mean * iv * LOG2E;
            sh_b2[tid] = -0.5f * mean * mean * iv * LOG2E;
        }
        __syncthreads();

        // Build A = a2_r * x_r, fused hi/lo layout
        {
            int row = tid >> 1, half = tid & 1;
            float a2 = sh_a2[row];
            const float* src = X + (size_t)(r0 + row) * DDIM;
            uint8_t* abase = sb + XS + row * 512;
#pragma unroll
            for (int kc = half * 4; kc < half * 4 + 4; kc++) {
#pragma unroll
                for (int qq = 0; qq < 4; qq++) {
                    int d = kc * 16 + qq * 2;
                    float2 v0 = *reinterpret_cast<const float2*>(src + d);
                    float2 v1 = *reinterpret_cast<const float2*>(src + d + 8);
                    uint32_t h0, l0, h1, l1;
                    split2(a2 * v0.x, a2 * v0.y, h0, l0);
                    split2(a2 * v1.x, a2 * v1.y, h1, l1);
                    *reinterpret_cast<uint4*>(abase + ((kc ^ (row & 7)) * 64 + qq * 16)) =
                        make_uint4(h0, h1, l0, l1);
                }
            }
        }

        const float b2a = sh_b2[rw + rsub];
        const float b2b = sh_b2[rw + rsub + 8];
        const uint8_t* arow1 = sb + XS + (rw + rsub) * 512;
        const uint8_t* arow2 = arow1 + 8 * 512;

        float o[16][4];
#pragma unroll
        for (int i = 0; i < 16; i++)
#pragma unroll
            for (int j = 0; j < 4; j++) o[i][j] = 0.0f;
        float m_a = -CUDART_INF_F, m_b = -CUDART_INF_F, l_a = 0.0f, l_b = 0.0f;

        for (int kt = t0; kt < t1; kt++) {
            const uint8_t* buf = sb + BUF0 + (kt & 1) * BUFSTRIDE;

            CP_WAIT0();
            __syncthreads();   // tile data visible; buf[kt-1] free for prefetch
            if (kt + 1 < t1) {
                prefetch_tile(sb0 + BUF0 + ((kt + 1) & 1) * BUFSTRIDE, kt + 1, tid);
                CP_COMMIT();
            }

            // ---- GEMM1 phase A: nf 0..3, all kc (completes s[0..3]) ----
            float s[8][4];
#pragma unroll
            for (int i = 0; i < 8; i++)
#pragma unroll
                for (int j = 0; j < 4; j++) s[i][j] = 0.0f;

            const float* y2p = (const float*)(buf + B_Y2);
            float mxa = -CUDART_INF_F, mxb = -CUDART_INF_F;

#pragma unroll
            for (int kc = 0; kc < 8; kc++) {
                uint32_t oA = (uint32_t)((kc ^ rsub) * 64 + lq * 16);
                uint4 ua = *reinterpret_cast<const uint4*>(arow1 + oA);
                uint4 ub = *reinterpret_cast<const uint4*>(arow2 + oA);
                uint32_t ah[4] = { ua.x, ub.x, ua.y, ub.y };
                uint32_t al[4] = { ua.z, ub.z, ua.w, ub.w };
                const uint8_t* bbase = buf + B_G1 + kc * 4096 + lane * 16;
#pragma unroll
                for (int nf = 0; nf < 4; nf++) {
                    uint4 bb = *reinterpret_cast<const uint4*>(bbase + nf * 512);
                    mma16816(s[nf], ah, bb.x, bb.y);
                    mma16816(s[nf], ah, bb.z, bb.w);
                    mma16816(s[nf], al, bb.x, bb.y);
                }
            }

            // ---- GEMM1 phase B: nf 4..7, with bias+max of s[0..3] interleaved ----
#pragma unroll
            for (int kc = 0; kc < 8; kc++) {
                uint32_t oA = (uint32_t)((kc ^ rsub) * 64 + lq * 16);
                uint4 ua = *reinterpret_cast<const uint4*>(arow1 + oA);
                uint4 ub = *reinterpret_cast<const uint4*>(arow2 + oA);
                uint32_t ah[4] = { ua.x, ub.x, ua.y, ub.y };
                uint32_t al[4] = { ua.z, ub.z, ua.w, ub.w };
                const uint8_t* bbase = buf + B_G1 + kc * 4096 + lane * 16;
#pragma unroll
                for (int nf = 4; nf < 8; nf++) {
                    uint4 bb = *reinterpret_cast<const uint4*>(bbase + nf * 512);
                    mma16816(s[nf], ah, bb.x, bb.y);
                    mma16816(s[nf], ah, bb.z, bb.w);
                    mma16816(s[nf], al, bb.x, bb.y);
                }
                if (kc & 1) {   // fragments 0..3 ready since phase A — hide bias+max here
                    int f = kc >> 1;
                    float2 y2v = *reinterpret_cast<const float2*>(y2p + f * 8 + lq * 2);
                    s[f][0] = fmaf(b2a, y2v.x, s[f][0]);
                    s[f][1] = fmaf(b2a, y2v.y, s[f][1]);
                    s[f][2] = fmaf(b2b, y2v.x, s[f][2]);
                    s[f][3] = fmaf(b2b, y2v.y, s[f][3]);
                    mxa = fmaxf(mxa, fmaxf(s[f][0], s[f][1]));
                    mxb = fmaxf(mxb, fmaxf(s[f][2], s[f][3]));
                }
            }

            // ---- bias + max for fragments 4..7 ----
#pragma unroll
            for (int f = 4; f < 8; f++) {
                float2 y2v = *reinterpret_cast<const float2*>(y2p + f * 8 + lq * 2);
                s[f][0] = fmaf(b2a, y2v.x, s[f][0]);
                s[f][1] = fmaf(b2a, y2v.y, s[f][1]);
                s[f][2] = fmaf(b2b, y2v.x, s[f][2]);
                s[f][3] = fmaf(b2b, y2v.y, s[f][3]);
                mxa = fmaxf(mxa, fmaxf(s[f][0], s[f][1]));
                mxb = fmaxf(mxb, fmaxf(s[f][2], s[f][3]));
            }
            mxa = fmaxf(mxa, __shfl_xor_sync(0xffffffffu, mxa, 1));
            mxa = fmaxf(mxa, __shfl_xor_sync(0xffffffffu, mxa, 2));
            mxb = fmaxf(mxb, __shfl_xor_sync(0xffffffffu, mxb, 1));
            mxb = fmaxf(mxb, __shfl_xor_sync(0xffffffffu, mxb, 2));
            float mna = fmaxf(m_a, mxa), mnb = fmaxf(m_b, mxb);

            // ---- rescale only when some row's max advanced ----
            bool upd = (mna > m_a) || (mnb > m_b);
            if (__any_sync(0xffffffffu, upd)) {
                float ala = ex2f(m_a - mna), alb = ex2f(m_b - mnb);
                l_a *= ala; l_b *= alb;
#pragma unroll
                for (int nf = 0; nf < 16; nf++) {
                    o[nf][0] *= ala; o[nf][1] *= ala;
                    o[nf][2] *= alb; o[nf][3] *= alb;
                }
                m_a = mna; m_b = mnb;
            }

            // ---- exp + split interleaved with GEMM2 ----
            float suma = 0.0f, sumb = 0.0f;
            uint32_t ph[16], pl[16];
            const uint8_t* bbase2 = buf + B_G2 + lane * 16;
#pragma unroll
            for (int f = 0; f < 4; f++) {
                float p0 = ex2f(s[f][0] - m_a), p1 = ex2f(s[f][1] - m_a);
                float p2 = ex2f(s[f][2] - m_b), p3 = ex2f(s[f][3] - m_b);
                suma += p0 + p1; sumb += p2 + p3;
                split2(p0, p1, ph[2 * f], pl[2 * f]);
                split2(p2, p3, ph[2 * f + 1], pl[2 * f + 1]);
            }
            {   // GEMM2 kc2 = 0
                uint32_t ah[4] = { ph[0], ph[1], ph[2], ph[3] };
                uint32_t al_[4] = { pl[0], pl[1], pl[2], pl[3] };
#pragma unroll
                for (int nf2 = 0; nf2 < 16; nf2++) {
                    uint4 bb = *reinterpret_cast<const uint4*>(bbase2 + nf2 * 512);
                    mma16816(o[nf2], ah, bb.x, bb.y);
                    mma16816(o[nf2], ah, bb.z, bb.w);
                    mma16816(o[nf2], al_, bb.x, bb.y);
                }
            }
#pragma unroll
            for (int f = 4; f < 8; f++) {
                float p0 = ex2f(s[f][0] - m_a), p1 = ex2f(s[f][1] - m_a);
                float p2 = ex2f(s[f][2] - m_b), p3 = ex2f(s[f][3] - m_b);
                suma += p0 + p1; sumb += p2 + p3;
                split2(p0, p1, ph[2 * f], pl[2 * f]);
                split2(p2, p3, ph[2 * f + 1], pl[2 * f + 1]);
            }
#pragma unroll
            for (int kc2 = 1; kc2 < 4; kc2++) {
                uint32_t ah[4] = { ph[4 * kc2], ph[4 * kc2 + 1], ph[4 * kc2 + 2], ph[4 * kc2 + 3] };
                uint32_t al_[4] = { pl[4 * kc2], pl[4 * kc2 + 1], pl[4 * kc2 + 2], pl[4 * kc2 + 3] };
                const uint8_t* bk = bbase2 + kc2 * 8192;
#pragma unroll
                for (int nf2 = 0; nf2 < 16; nf2++) {
                    uint4 bb = *reinterpret_cast<const uint4*>(bk + nf2 * 512);
                    mma16816(o[nf2], ah, bb.x, bb.y);
                    mma16816(o[nf2], ah, bb.z, bb.w);
                    mma16816(o[nf2], al_, bb.x, bb.y);
                }
            }

            suma += __shfl_xor_sync(0xffffffffu, suma, 1);
            suma += __shfl_xor_sync(0xffffffffu, suma, 2);
            sumb += __shfl_xor_sync(0xffffffffu, sumb, 1);
            sumb += __shfl_xor_sync(0xffffffffu, sumb, 2);
            l_a += suma;
            l_b += sumb;
        }

        // ---- write segment partials into this rowblock's slot ----
        {
            int ga = r0 + rw + rsub;
            int gbrow = ga + 8;
            if (lq == 0) {
                g_pm[slot * NROWS + ga] = m_a;   g_pl[slot * NROWS + ga] = l_a;
                g_pm[slot * NROWS + gbrow] = m_b; g_pl[slot * NROWS + gbrow] = l_b;
            }
            float* da = g_pO + ((size_t)(slot * NROWS + ga)) * DDIM + lq * 2;
            float* db = g_pO + ((size_t)(slot * NROWS + gbrow)) * DDIM + lq * 2;
#pragma unroll
            for (int nf = 0; nf < 16; nf++) {
                *reinterpret_cast<float2*>(da + nf * 8) = make_float2(o[nf][0], o[nf][1]);
                *reinterpret_cast<float2*>(db + nf * 8) = make_float2(o[nf][2], o[nf][3]);
            }
        }

        u = ue;
    }
}

// ---------------- merge slots + epilogue ----------------
__global__ void gmm_merge_kernel(const float* __restrict__ X, const float* __restrict__ T,
                                 float* __restrict__ out) {
    int row = blockIdx.x * 2 + (threadIdx.x >> 7);
    int d = threadIdx.x & 127;
    float tv = T[row];
    float lm = -0.25f * tv * tv * (BETA_MAX - BETA_MIN) - 0.5f * tv * BETA_MIN;
    float var = fmaxf(1.0f - expf(2.0f * lm), 1e-12f);
    float iv = 1.0f / var;
    float M = -CUDART_INF_F;
    float pm[NSLOT];
#pragma unroll
    for (int s = 0; s < NSLOT; s++) {
        pm[s] = g_pm[s * NROWS + row];
        M = fmaxf(M, pm[s]);
    }
    float L = 0.0f, O = 0.0f;
#pragma unroll
    for (int s = 0; s < NSLOT; s++) {
        if (pm[s] > -1e30f) {
            float w = fexp2(pm[s] - M);
            L += g_pl[s * NROWS + row] * w;
            O += g_pO[((size_t)(s * NROWS + row)) * DDIM + d] * w;
        }
    }
    out[(size_t)row * DDIM + d] = (O / L - X[(size_t)row * DDIM + d]) * iv;
}

// ---------------------------------------------------------------------------
extern "C" void kernel_launch(void* const* d_in, const int* in_sizes, int n_in,
                              void* d_out, int out_size) {
    (void)n_in; (void)out_size;
    const float* x = (const float*)d_in[0];
    const float* t = (const float*)d_in[1];
    const float* y = (const float*)d_in[2];
    float* out = (float*)d_out;

    cudaFuncSetAttribute(gmm_main_kernel,
                         cudaFuncAttributeMaxDynamicSharedMemorySize, SMEM_BYTES);

    gmm_init_kernel<<<NSLOT * NROWS / 1024, 256>>>();
    gmm_prep_kernel<<<TILES_ALL, 256>>>(y);
    gmm_main_kernel<<<NCTA, 256, SMEM_BYTES>>>(x, t);
    gmm_merge_kernel<<<NROWS / 2, 256>>>(x, t, out);
}

// round 16
// speedup vs baseline: 1.6939x; 1.0048x over previous
#include <cuda_runtime.h>
#include <cuda_bf16.h>
#include <math_constants.h>
#include <cstdint>

#define BETA_MIN 0.1f
#define BETA_MAX 20.0f
#define LOG2E 1.4426950408889634f
#define DDIM 128
#define NROWS 4096
#define MKEYS 16384
#define BM 128
#define BN 32                 // keys per tile (halved for ping-pong buffers)
#define TILES_ALL 512
#define NCTA 148
#define NUNITS 2048           // 32 rowblocks x 64 chunks (8 tiles each)
#define NSLOT 8

// smem layout
#define XS   0                 // A tile fused hi/lo: 128 rows * 512B = 64KB
#define BUF0 65536
#define HSTRIDE 66048          // per-half buffer region (2 x 33024)
#define TBUF 33024             // one tile buffer: G1 16KB + G2 16KB + y2 pad
#define B_G2 16384
#define B_Y2 32768
#define SMEM_BYTES (BUF0 + 2 * HSTRIDE)   // 197632

#define YSTRIDE 132

__device__ float g_y2[MKEYS];
__device__ uint4 g_yc1[TILES_ALL * 1024];   // GEMM1 fused blobs (BN=32)
__device__ uint4 g_yc2[TILES_ALL * 1024];   // GEMM2 fused blobs
__device__ float g_pO[(size_t)NSLOT * NROWS * DDIM];
__device__ float g_pm[NSLOT * NROWS];
__device__ float g_pl[NSLOT * NROWS];

// ---------------- helpers ----------------
__device__ __forceinline__ uint32_t smem_u32(const void* p) {
    uint32_t a;
    asm("{ .reg .u64 t; cvta.to.shared.u64 t, %1; cvt.u32.u64 %0, t; }" : "=r"(a) : "l"(p));
    return a;
}
__device__ __forceinline__ float ex2f(float v) {
    float r;
    asm("ex2.approx.f32 %0, %1;" : "=f"(r) : "f"(v));
    return r;
}
__device__ __forceinline__ float fexp2(float v) {
    v = fmaxf(v, -30.0f);
    float r = v + 12582912.0f;
    int   n = __float_as_int(r) - 0x4B400000;
    float f = v - (r - 12582912.0f);
    float p = 1.3333558146e-3f;
    p = fmaf(p, f, 9.6181291918e-3f);
    p = fmaf(p, f, 5.5504108664e-2f);
    p = fmaf(p, f, 2.4022650696e-1f);
    p = fmaf(p, f, 6.9314718056e-1f);
    p = fmaf(p, f, 1.0f);
    return __int_as_float(__float_as_int(p) + (n << 23));
}
__device__ __forceinline__ void split2(float a, float b, uint32_t& h, uint32_t& l) {
    uint32_t hp, lp;
    asm("cvt.rn.bf16x2.f32 %0, %1, %2;" : "=r"(hp) : "f"(b), "f"(a));
    float ra = a - __int_as_float(hp << 16);
    float rb = b - __int_as_float(hp & 0xFFFF0000u);
    asm("cvt.rn.bf16x2.f32 %0, %1, %2;" : "=r"(lp) : "f"(rb), "f"(ra));
    h = hp; l = lp;
}
__device__ __forceinline__ void mma16816(float* c, const uint32_t* a, uint32_t b0, uint32_t b1) {
    asm volatile("mma.sync.aligned.m16n8k16.row.col.f32.bf16.bf16.f32 "
        "{%0,%1,%2,%3}, {%4,%5,%6,%7}, {%8,%9}, {%0,%1,%2,%3};"
        : "+f"(c[0]), "+f"(c[1]), "+f"(c[2]), "+f"(c[3])
        : "r"(a[0]), "r"(a[1]), "r"(a[2]), "r"(a[3]), "r"(b0), "r"(b1));
}
__device__ __forceinline__ void cpa16(uint32_t s, const void* g) {
    asm volatile("cp.async.cg.shared.global [%0], [%1], 16;" :: "r"(s), "l"(g));
}
#define CP_COMMIT() asm volatile("cp.async.commit_group;" ::: "memory")
#define CP_WAIT0()  asm volatile("cp.async.wait_group 0;" ::: "memory")
// named barrier: half h = warps 4h..4h+3 (128 threads)
#define BARH(h) asm volatile("bar.sync %0, %1;" :: "r"((h) + 1), "r"(128) : "memory")

// per-half tile prefetch: 128 threads copy 16KB G1 + 16KB G2 + 128B y2
__device__ __forceinline__ void prefetch_half(uint32_t dst, int tg, int ht) {
    const uint4* s1 = g_yc1 + tg * 1024;
    const uint4* s2 = g_yc2 + tg * 1024;
#pragma unroll
    for (int i = 0; i < 8; i++) {
        int idx = ht + 128 * i;
        cpa16(dst + idx * 16, s1 + idx);
        cpa16(dst + B_G2 + idx * 16, s2 + idx);
    }
    if (ht < 8) cpa16(dst + B_Y2 + ht * 16, ((const uint4*)(g_y2 + tg * BN)) + ht);
}

__device__ __forceinline__ int ustart(int b) { return (b * NUNITS) / NCTA; }

// ---------------- init: reset partial maxima ----------------
__global__ void gmm_init_kernel() {
    int i = (blockIdx.x * 256 + threadIdx.x) * 4;
    *reinterpret_cast<float4*>(g_pm + i) =
        make_float4(-CUDART_INF_F, -CUDART_INF_F, -CUDART_INF_F, -CUDART_INF_F);
}

// ---------------- precompute: fused blobs + y2 (BN=32 tiles) ----------------
__global__ void gmm_prep_kernel(const float* __restrict__ Y) {
    __shared__ float ys[BN * YSTRIDE];
    const int tile = blockIdx.x, tid = threadIdx.x;
    const float* src = Y + (size_t)tile * BN * DDIM;
#pragma unroll
    for (int i = 0; i < 4; i++) {
        int idx = tid + 256 * i;          // 1024 float4 total
        int row = idx >> 5;               // 32 float4 per row
        int col = (idx & 31) * 4;
        *reinterpret_cast<float4*>(ys + row * YSTRIDE + col) =
            *reinterpret_cast<const float4*>(src + row * DDIM + col);
    }
    __syncthreads();

    // y2: 4 threads per key row (rows 0..31 -> threads 0..127)
    if (tid < 128) {
        int row = tid >> 2, part = tid & 3;
        const float* r = ys + row * YSTRIDE + part * 32;
        float s = 0.0f;
#pragma unroll
        for (int i = 0; i < 32; i += 4) {
            float4 v = *reinterpret_cast<const float4*>(r + i);
            s += v.x * v.x + v.y * v.y + v.z * v.z + v.w * v.w;
        }
        s += __shfl_xor_sync(0xffffffffu, s, 1);
        s += __shfl_xor_sync(0xffffffffu, s, 2);
        if (part == 0) g_y2[tile * BN + row] = s;
    }

    // GEMM1 blob: slot s -> kc = s>>7, nf = (s>>5)&3, rs = (s>>2)&7, q = s&3
#pragma unroll
    for (int j = 0; j < 4; j++) {
        int s = tid + 256 * j;
        int kc = s >> 7, nf = (s >> 5) & 3, rs = (s >> 2) & 7, q = s & 3;
        int n = nf * 8 + rs, kb = kc * 16 + q * 2;
        const float* row = ys + n * YSTRIDE;
        uint32_t h0, l0, h1, l1;
        split2(row[kb], row[kb + 1], h0, l0);
        split2(row[kb + 8], row[kb + 9], h1, l1);
        g_yc1[tile * 1024 + s] = make_uint4(h0, h1, l0, l1);
    }
    // GEMM2 blob: slot s -> kc2 = s>>9, nf2 = (s>>5)&15, rs = (s>>2)&7, q = s&3
#pragma unroll
    for (int j = 0; j < 4; j++) {
        int s = tid + 256 * j;
        int kc2 = s >> 9, nf2 = (s >> 5) & 15, rs = (s >> 2) & 7, q = s & 3;
        int d = nf2 * 8 + rs, k = kc2 * 16 + q * 2;
        uint32_t h0, l0, h1, l1;
        split2(ys[k * YSTRIDE + d], ys[(k + 1) * YSTRIDE + d], h0, l0);
        split2(ys[(k + 8) * YSTRIDE + d], ys[(k + 9) * YSTRIDE + d], h1, l1);
        g_yc2[tile * 1024 + s] = make_uint4(h0, h1, l0, l1);
    }
}

// ---------------- main fused kernel: persistent, ping-pong half warp-groups --------
__global__ __launch_bounds__(256, 1)
void gmm_main_kernel(const float* __restrict__ X, const float* __restrict__ T) {
    extern __shared__ uint8_t sb[];
    __shared__ float sh_a2[BM], sh_b2[BM];

    const int tid = threadIdx.x, lane = tid & 31, wid = tid >> 5;
    const int h = wid >> 2;            // half 0: warps 0-3 (rows 0-63); half 1: warps 4-7
    const int lw = wid & 3;            // warp within half
    const int ht = tid & 127;          // thread within half
    const int rsub = lane >> 2;
    const int lq = lane & 3;
    const uint32_t sb0 = smem_u32(sb);
    const uint32_t hbase = sb0 + BUF0 + h * HSTRIDE;
    const int b = blockIdx.x;
    const int u0 = ustart(b), u1 = ustart(b + 1);

    int u = u0;
    while (u < u1) {
        const int rb = u >> 6;                  // 64 units per rowblock
        const int ue = min(u1, (rb + 1) * 64);
        const int t0 = (u - (rb << 6)) * 8;     // first BN=32 tile (global tile id base rb*512... no: per-rowblock tiles 0..511)
        const int t1 = (ue - (rb << 6)) * 8;
        const int r0 = rb * BM;

        // slot = b - b_first(rb)
        int bf = (int)(((long long)(rb << 6) * NCTA) >> 11);
        while (ustart(bf + 1) <= (rb << 6)) bf++;
        while (ustart(bf) > (rb << 6)) bf--;
        const int slot = b - bf;

        BARH(h);   // this half's warps done with previous segment (XS half, sh arrays)

        // prefetch first tile of segment ASAP (into this half's buffer)
        prefetch_half(hbase + (t0 & 1) * TBUF, t0, ht);
        CP_COMMIT();

        if (ht < 64) {
            int row = h * 64 + ht;
            float tv = T[r0 + row];
            float lm = -0.25f * tv * tv * (BETA_MAX - BETA_MIN) - 0.5f * tv * BETA_MIN;
            float mean = expf(lm);
            float var = fmaxf(1.0f - expf(2.0f * lm), 1e-12f);
            float iv = 1.0f / var;
            sh_a2[row] = mean * iv * LOG2E;
            sh_b2[row] = -0.5f * mean * mean * iv * LOG2E;
        }
        BARH(h);

        // Build this half's A rows: fused hi/lo layout row*512 + (kc^(row&7))*64 + q*16
        {
            int row = h * 64 + (ht >> 1), rhalf = ht & 1;
            float a2 = sh_a2[row];
            const float* src = X + (size_t)(r0 + row) * DDIM;
            uint8_t* abase = sb + XS + row * 512;
#pragma unroll
            for (int kc = rhalf * 4; kc < rhalf * 4 + 4; kc++) {
#pragma unroll
                for (int qq = 0; qq < 4; qq++) {
                    int d = kc * 16 + qq * 2;
                    float2 v0 = *reinterpret_cast<const float2*>(src + d);
                    float2 v1 = *reinterpret_cast<const float2*>(src + d + 8);
                    uint32_t h0, l0, h1, l1;
                    split2(a2 * v0.x, a2 * v0.y, h0, l0);
                    split2(a2 * v1.x, a2 * v1.y, h1, l1);
                    *reinterpret_cast<uint4*>(abase + ((kc ^ (row & 7)) * 64 + qq * 16)) =
                        make_uint4(h0, h1, l0, l1);
                }
            }
        }

        const int rloc = h * 64 + lw * 16 + rsub;      // this thread's first row (CTA-local)
        const float b2a = sh_b2[rloc];
        const float b2b = sh_b2[rloc + 8];
        const uint8_t* arow1 = sb + XS + rloc * 512;
        const uint8_t* arow2 = arow1 + 8 * 512;

        float o[16][4];
#pragma unroll
        for (int i = 0; i < 16; i++)
#pragma unroll
            for (int j = 0; j < 4; j++) o[i][j] = 0.0f;
        float m_a = -CUDART_INF_F, m_b = -CUDART_INF_F, l_a = 0.0f, l_b = 0.0f;

        for (int kt = t0; kt < t1; kt++) {
            const uint8_t* buf = sb + BUF0 + h * HSTRIDE + (kt & 1) * TBUF;

            CP_WAIT0();
            BARH(h);   // tile visible to this half; prev buffer free
            if (kt + 1 < t1) {
                prefetch_half(hbase + ((kt + 1) & 1) * TBUF, kt + 1, ht);
                CP_COMMIT();
            }

            // ---- GEMM1: S[16][32] per warp, 3-term bf16 split, K=128 ----
            float s[4][4];
#pragma unroll
            for (int i = 0; i < 4; i++)
#pragma unroll
                for (int j = 0; j < 4; j++) s[i][j] = 0.0f;

#pragma unroll
            for (int kc = 0; kc < 8; kc++) {
                uint32_t oA = (uint32_t)((kc ^ rsub) * 64 + lq * 16);
                uint4 ua = *reinterpret_cast<const uint4*>(arow1 + oA);
                uint4 ub = *reinterpret_cast<const uint4*>(arow2 + oA);
                uint32_t ah[4] = { ua.x, ub.x, ua.y, ub.y };
                uint32_t al[4] = { ua.z, ub.z, ua.w, ub.w };
                const uint8_t* bbase = buf + kc * 2048 + lane * 16;
#pragma unroll
                for (int nf = 0; nf < 4; nf++) {
                    uint4 bb = *reinterpret_cast<const uint4*>(bbase + nf * 512);
                    mma16816(s[nf], ah, bb.x, bb.y);
                    mma16816(s[nf], ah, bb.z, bb.w);
                    mma16816(s[nf], al, bb.x, bb.y);
                }
            }

            // ---- bias + row max ----
            const float* y2p = (const float*)(buf + B_Y2);
            float mxa = -CUDART_INF_F, mxb = -CUDART_INF_F;
#pragma unroll
            for (int f = 0; f < 4; f++) {
                float2 y2v = *reinterpret_cast<const float2*>(y2p + f * 8 + lq * 2);
                s[f][0] = fmaf(b2a, y2v.x, s[f][0]);
                s[f][1] = fmaf(b2a, y2v.y, s[f][1]);
                s[f][2] = fmaf(b2b, y2v.x, s[f][2]);
                s[f][3] = fmaf(b2b, y2v.y, s[f][3]);
                mxa = fmaxf(mxa, fmaxf(s[f][0], s[f][1]));
                mxb = fmaxf(mxb, fmaxf(s[f][2], s[f][3]));
            }
            mxa = fmaxf(mxa, __shfl_xor_sync(0xffffffffu, mxa, 1));
            mxa = fmaxf(mxa, __shfl_xor_sync(0xffffffffu, mxa, 2));
            mxb = fmaxf(mxb, __shfl_xor_sync(0xffffffffu, mxb, 1));
            mxb = fmaxf(mxb, __shfl_xor_sync(0xffffffffu, mxb, 2));
            float mna = fmaxf(m_a, mxa), mnb = fmaxf(m_b, mxb);

            // ---- rescale only when some row's max advanced ----
            bool upd = (mna > m_a) || (mnb > m_b);
            if (__any_sync(0xffffffffu, upd)) {
                float ala = ex2f(m_a - mna), alb = ex2f(m_b - mnb);
                l_a *= ala; l_b *= alb;
#pragma unroll
                for (int nf = 0; nf < 16; nf++) {
                    o[nf][0] *= ala; o[nf][1] *= ala;
                    o[nf][2] *= alb; o[nf][3] *= alb;
                }
                m_a = mna; m_b = mnb;
            }

            // ---- exp + split interleaved with GEMM2 (K=32, 3-term split) ----
            float suma = 0.0f, sumb = 0.0f;
            uint32_t ph[8], pl[8];
            const uint8_t* bbase2 = buf + B_G2 + lane * 16;
#pragma unroll
            for (int f = 0; f < 2; f++) {
                float p0 = ex2f(s[f][0] - m_a), p1 = ex2f(s[f][1] - m_a);
                float p2 = ex2f(s[f][2] - m_b), p3 = ex2f(s[f][3] - m_b);
                suma += p0 + p1; sumb += p2 + p3;
                split2(p0, p1, ph[2 * f], pl[2 * f]);
                split2(p2, p3, ph[2 * f + 1], pl[2 * f + 1]);
            }
            {   // GEMM2 kc2 = 0
                uint32_t ah[4] = { ph[0], ph[1], ph[2], ph[3] };
                uint32_t al_[4] = { pl[0], pl[1], pl[2], pl[3] };
#pragma unroll
                for (int nf2 = 0; nf2 < 16; nf2++) {
                    uint4 bb = *reinterpret_cast<const uint4*>(bbase2 + nf2 * 512);
                    mma16816(o[nf2], ah, bb.x, bb.y);
                    mma16816(o[nf2], ah, bb.z, bb.w);
                    mma16816(o[nf2], al_, bb.x, bb.y);
                }
            }
#pragma unroll
            for (int f = 2; f < 4; f++) {
                float p0 = ex2f(s[f][0] - m_a), p1 = ex2f(s[f][1] - m_a);
                float p2 = ex2f(s[f][2] - m_b), p3 = ex2f(s[f][3] - m_b);
                suma += p0 + p1; sumb += p2 + p3;
                split2(p0, p1, ph[2 * f], pl[2 * f]);
                split2(p2, p3, ph[2 * f + 1], pl[2 * f + 1]);
            }
            {   // GEMM2 kc2 = 1
                uint32_t ah[4] = { ph[4], ph[5], ph[6], ph[7] };
                uint32_t al_[4] = { pl[4], pl[5], pl[6], pl[7] };
                const uint8_t* bk = bbase2 + 8192;
#pragma unroll
                for (int nf2 = 0; nf2 < 16; nf2++) {
                    uint4 bb = *reinterpret_cast<const uint4*>(bk + nf2 * 512);
                    mma16816(o[nf2], ah, bb.x, bb.y);
                    mma16816(o[nf2], ah, bb.z, bb.w);
                    mma16816(o[nf2], al_, bb.x, bb.y);
                }
            }

            // ---- deferred l reduction ----
            suma += __shfl_xor_sync(0xffffffffu, suma, 1);
            suma += __shfl_xor_sync(0xffffffffu, suma, 2);
            sumb += __shfl_xor_sync(0xffffffffu, sumb, 1);
            sumb += __shfl_xor_sync(0xffffffffu, sumb, 2);
            l_a += suma;
            l_b += sumb;
        }

        // ---- write segment partials into this rowblock's slot ----
        {
            int ga = r0 + rloc;
            int gbrow = ga + 8;
            if (lq == 0) {
                g_pm[slot * NROWS + ga] = m_a;   g_pl[slot * NROWS + ga] = l_a;
                g_pm[slot * NROWS + gbrow] = m_b; g_pl[slot * NROWS + gbrow] = l_b;
            }
            float* da = g_pO + ((size_t)(slot * NROWS + ga)) * DDIM + lq * 2;
            float* db = g_pO + ((size_t)(slot * NROWS + gbrow)) * DDIM + lq * 2;
#pragma unroll
            for (int nf = 0; nf < 16; nf++) {
                *reinterpret_cast<float2*>(da + nf * 8) = make_float2(o[nf][0], o[nf][1]);
                *reinterpret_cast<float2*>(db + nf * 8) = make_float2(o[nf][2], o[nf][3]);
            }
        }

        u = ue;
    }
}

// ---------------- merge slots + epilogue ----------------
__global__ void gmm_merge_kernel(const float* __restrict__ X, const float* __restrict__ T,
                                 float* __restrict__ out) {
    int row = blockIdx.x * 2 + (threadIdx.x >> 7);
    int d = threadIdx.x & 127;
    float tv = T[row];
    float lm = -0.25f * tv * tv * (BETA_MAX - BETA_MIN) - 0.5f * tv * BETA_MIN;
    float var = fmaxf(1.0f - expf(2.0f * lm), 1e-12f);
    float iv = 1.0f / var;
    float M = -CUDART_INF_F;
    float pm[NSLOT];
#pragma unroll
    for (int s = 0; s < NSLOT; s++) {
        pm[s] = g_pm[s * NROWS + row];
        M = fmaxf(M, pm[s]);
    }
    float L = 0.0f, O = 0.0f;
#pragma unroll
    for (int s = 0; s < NSLOT; s++) {
        if (pm[s] > -1e30f) {
            float w = fexp2(pm[s] - M);
            L += g_pl[s * NROWS + row] * w;
            O += g_pO[((size_t)(s * NROWS + row)) * DDIM + d] * w;
        }
    }
    out[(size_t)row * DDIM + d] = (O / L - X[(size_t)row * DDIM + d]) * iv;
}

// ---------------------------------------------------------------------------
extern "C" void kernel_launch(void* const* d_in, const int* in_sizes, int n_in,
                              void* d_out, int out_size) {
    (void)n_in; (void)out_size;
    const float* x = (const float*)d_in[0];
    const float* t = (const float*)d_in[1];
    const float* y = (const float*)d_in[2];
    float* out = (float*)d_out;

    cudaFuncSetAttribute(gmm_main_kernel,
                         cudaFuncAttributeMaxDynamicSharedMemorySize, SMEM_BYTES);

    gmm_init_kernel<<<NSLOT * NROWS / 1024, 256>>>();
    gmm_prep_kernel<<<TILES_ALL, 256>>>(y);
    gmm_main_kernel<<<NCTA, 256, SMEM_BYTES>>>(x, t);
    gmm_merge_kernel<<<NROWS / 2, 256>>>(x, t, out);
}

// round 17
// speedup vs baseline: 1.8528x; 1.0938x over previous
#include <cuda_runtime.h>
#include <cuda_bf16.h>
#include <cuda_fp16.h>
#include <math_constants.h>
#include <cstdint>

#define BETA_MIN 0.1f
#define BETA_MAX 20.0f
#define LOG2E 1.4426950408889634f
#define DDIM 128
#define NROWS 4096
#define MKEYS 16384
#define BM 128
#define BN 32                 // keys per tile
#define TILES_ALL 512
#define NCTA 148
#define NUNITS 2048           // 32 rowblocks x 64 chunks (8 tiles each)
#define NSLOT 8

// smem layout
#define XS   0                 // A tile fused hi/lo: 128 rows * 512B = 64KB
#define BUF0 65536
#define HSTRIDE 66048          // per-half buffer region (2 x 33024)
#define TBUF 33024             // one tile buffer: G1 16KB + G2 16KB + y2 pad
#define B_G2 16384
#define B_Y2 32768
#define SMEM_BYTES (BUF0 + 2 * HSTRIDE)   // 197632

#define YSTRIDE 132

__device__ float g_y2[MKEYS];
__device__ uint4 g_yc1[TILES_ALL * 1024];   // GEMM1 fused blobs (bf16 hi/lo)
__device__ uint4 g_yc2[TILES_ALL * 1024];   // GEMM2 fused blobs (fp16 hi/lo)
__device__ float g_pO[(size_t)NSLOT * NROWS * DDIM];
__device__ float g_pm[NSLOT * NROWS];
__device__ float g_pl[NSLOT * NROWS];

// ---------------- helpers ----------------
__device__ __forceinline__ uint32_t smem_u32(const void* p) {
    uint32_t a;
    asm("{ .reg .u64 t; cvta.to.shared.u64 t, %1; cvt.u32.u64 %0, t; }" : "=r"(a) : "l"(p));
    return a;
}
__device__ __forceinline__ float ex2f(float v) {
    float r;
    asm("ex2.approx.f32 %0, %1;" : "=f"(r) : "f"(v));
    return r;
}
__device__ __forceinline__ float fexp2(float v) {
    v = fmaxf(v, -30.0f);
    float r = v + 12582912.0f;
    int   n = __float_as_int(r) - 0x4B400000;
    float f = v - (r - 12582912.0f);
    float p = 1.3333558146e-3f;
    p = fmaf(p, f, 9.6181291918e-3f);
    p = fmaf(p, f, 5.5504108664e-2f);
    p = fmaf(p, f, 2.4022650696e-1f);
    p = fmaf(p, f, 6.9314718056e-1f);
    p = fmaf(p, f, 1.0f);
    return __int_as_float(__float_as_int(p) + (n << 23));
}
// split (a,b) -> bf16x2 hi (low half = a) + bf16x2 lo residual
__device__ __forceinline__ void split2(float a, float b, uint32_t& h, uint32_t& l) {
    uint32_t hp, lp;
    asm("cvt.rn.bf16x2.f32 %0, %1, %2;" : "=r"(hp) : "f"(b), "f"(a));
    float ra = a - __int_as_float(hp << 16);
    float rb = b - __int_as_float(hp & 0xFFFF0000u);
    asm("cvt.rn.bf16x2.f32 %0, %1, %2;" : "=r"(lp) : "f"(rb), "f"(ra));
    h = hp; l = lp;
}
// split (a,b) -> f16x2 hi (low half = a) + f16x2 lo residual
__device__ __forceinline__ void split2h(float a, float b, uint32_t& h, uint32_t& l) {
    uint32_t hp, lp;
    asm("cvt.rn.f16x2.f32 %0, %1, %2;" : "=r"(hp) : "f"(b), "f"(a));
    __half2 hh = *reinterpret_cast<__half2*>(&hp);
    float ra = a - __low2float(hh);
    float rb = b - __high2float(hh);
    asm("cvt.rn.f16x2.f32 %0, %1, %2;" : "=r"(lp) : "f"(rb), "f"(ra));
    h = hp; l = lp;
}
__device__ __forceinline__ uint32_t pack_f16x2(float a, float b) {
    uint32_t r;
    asm("cvt.rn.f16x2.f32 %0, %1, %2;" : "=r"(r) : "f"(b), "f"(a));
    return r;
}
__device__ __forceinline__ void mma16816(float* c, const uint32_t* a, uint32_t b0, uint32_t b1) {
    asm volatile("mma.sync.aligned.m16n8k16.row.col.f32.bf16.bf16.f32 "
        "{%0,%1,%2,%3}, {%4,%5,%6,%7}, {%8,%9}, {%0,%1,%2,%3};"
        : "+f"(c[0]), "+f"(c[1]), "+f"(c[2]), "+f"(c[3])
        : "r"(a[0]), "r"(a[1]), "r"(a[2]), "r"(a[3]), "r"(b0), "r"(b1));
}
__device__ __forceinline__ void mma16816h(float* c, const uint32_t* a, uint32_t b0, uint32_t b1) {
    asm volatile("mma.sync.aligned.m16n8k16.row.col.f32.f16.f16.f32 "
        "{%0,%1,%2,%3}, {%4,%5,%6,%7}, {%8,%9}, {%0,%1,%2,%3};"
        : "+f"(c[0]), "+f"(c[1]), "+f"(c[2]), "+f"(c[3])
        : "r"(a[0]), "r"(a[1]), "r"(a[2]), "r"(a[3]), "r"(b0), "r"(b1));
}
__device__ __forceinline__ void cpa16(uint32_t s, const void* g) {
    asm volatile("cp.async.cg.shared.global [%0], [%1], 16;" :: "r"(s), "l"(g));
}
#define CP_COMMIT() asm volatile("cp.async.commit_group;" ::: "memory")
#define CP_WAIT0()  asm volatile("cp.async.wait_group 0;" ::: "memory")
#define BARH(h) asm volatile("bar.sync %0, %1;" :: "r"((h) + 1), "r"(128) : "memory")

__device__ __forceinline__ void prefetch_half(uint32_t dst, int tg, int ht) {
    const uint4* s1 = g_yc1 + tg * 1024;
    const uint4* s2 = g_yc2 + tg * 1024;
#pragma unroll
    for (int i = 0; i < 8; i++) {
        int idx = ht + 128 * i;
        cpa16(dst + idx * 16, s1 + idx);
        cpa16(dst + B_G2 + idx * 16, s2 + idx);
    }
    if (ht < 8) cpa16(dst + B_Y2 + ht * 16, ((const uint4*)(g_y2 + tg * BN)) + ht);
}

__device__ __forceinline__ int ustart(int b) { return (b * NUNITS) / NCTA; }

// ---------------- init: reset partial maxima ----------------
__global__ void gmm_init_kernel() {
    int i = (blockIdx.x * 256 + threadIdx.x) * 4;
    *reinterpret_cast<float4*>(g_pm + i) =
        make_float4(-CUDART_INF_F, -CUDART_INF_F, -CUDART_INF_F, -CUDART_INF_F);
}

// ---------------- precompute: fused blobs + y2 (BN=32 tiles) ----------------
__global__ void gmm_prep_kernel(const float* __restrict__ Y) {
    __shared__ float ys[BN * YSTRIDE];
    const int tile = blockIdx.x, tid = threadIdx.x;
    const float* src = Y + (size_t)tile * BN * DDIM;
#pragma unroll
    for (int i = 0; i < 4; i++) {
        int idx = tid + 256 * i;
        int row = idx >> 5;
        int col = (idx & 31) * 4;
        *reinterpret_cast<float4*>(ys + row * YSTRIDE + col) =
            *reinterpret_cast<const float4*>(src + row * DDIM + col);
    }
    __syncthreads();

    if (tid < 128) {
        int row = tid >> 2, part = tid & 3;
        const float* r = ys + row * YSTRIDE + part * 32;
        float s = 0.0f;
#pragma unroll
        for (int i = 0; i < 32; i += 4) {
            float4 v = *reinterpret_cast<const float4*>(r + i);
            s += v.x * v.x + v.y * v.y + v.z * v.z + v.w * v.w;
        }
        s += __shfl_xor_sync(0xffffffffu, s, 1);
        s += __shfl_xor_sync(0xffffffffu, s, 2);
        if (part == 0) g_y2[tile * BN + row] = s;
    }

    // GEMM1 blob (bf16): slot s -> kc = s>>7, nf = (s>>5)&3, rs = (s>>2)&7, q = s&3
#pragma unroll
    for (int j = 0; j < 4; j++) {
        int s = tid + 256 * j;
        int kc = s >> 7, nf = (s >> 5) & 3, rs = (s >> 2) & 7, q = s & 3;
        int n = nf * 8 + rs, kb = kc * 16 + q * 2;
        const float* row = ys + n * YSTRIDE;
        uint32_t h0, l0, h1, l1;
        split2(row[kb], row[kb + 1], h0, l0);
        split2(row[kb + 8], row[kb + 9], h1, l1);
        g_yc1[tile * 1024 + s] = make_uint4(h0, h1, l0, l1);
    }
    // GEMM2 blob (fp16): slot s -> kc2 = s>>9, nf2 = (s>>5)&15, rs = (s>>2)&7, q = s&3
#pragma unroll
    for (int j = 0; j < 4; j++) {
        int s = tid + 256 * j;
        int kc2 = s >> 9, nf2 = (s >> 5) & 15, rs = (s >> 2) & 7, q = s & 3;
        int d = nf2 * 8 + rs, k = kc2 * 16 + q * 2;
        uint32_t h0, l0, h1, l1;
        split2h(ys[k * YSTRIDE + d], ys[(k + 1) * YSTRIDE + d], h0, l0);
        split2h(ys[(k + 8) * YSTRIDE + d], ys[(k + 9) * YSTRIDE + d], h1, l1);
        g_yc2[tile * 1024 + s] = make_uint4(h0, h1, l0, l1);
    }
}

// ---------------- main fused kernel: persistent, ping-pong half warp-groups --------
__global__ __launch_bounds__(256, 1)
void gmm_main_kernel(const float* __restrict__ X, const float* __restrict__ T) {
    extern __shared__ uint8_t sb[];
    __shared__ float sh_a2[BM], sh_b2[BM];

    const int tid = threadIdx.x, lane = tid & 31, wid = tid >> 5;
    const int h = wid >> 2;
    const int lw = wid & 3;
    const int ht = tid & 127;
    const int rsub = lane >> 2;
    const int lq = lane & 3;
    const uint32_t sb0 = smem_u32(sb);
    const uint32_t hbase = sb0 + BUF0 + h * HSTRIDE;
    const int b = blockIdx.x;
    const int u0 = ustart(b), u1 = ustart(b + 1);

    int u = u0;
    while (u < u1) {
        const int rb = u >> 6;
        const int ue = min(u1, (rb + 1) * 64);
        const int t0 = (u - (rb << 6)) * 8;
        const int t1 = (ue - (rb << 6)) * 8;
        const int r0 = rb * BM;

        int bf = (int)(((long long)(rb << 6) * NCTA) >> 11);
        while (ustart(bf + 1) <= (rb << 6)) bf++;
        while (ustart(bf) > (rb << 6)) bf--;
        const int slot = b - bf;

        BARH(h);

        prefetch_half(hbase + (t0 & 1) * TBUF, t0, ht);
        CP_COMMIT();

        if (ht < 64) {
            int row = h * 64 + ht;
            float tv = T[r0 + row];
            float lm = -0.25f * tv * tv * (BETA_MAX - BETA_MIN) - 0.5f * tv * BETA_MIN;
            float mean = expf(lm);
            float var = fmaxf(1.0f - expf(2.0f * lm), 1e-12f);
            float iv = 1.0f / var;
            sh_a2[row] = mean * iv * LOG2E;
            sh_b2[row] = -0.5f * mean * mean * iv * LOG2E;
        }
        BARH(h);

        // Build this half's A rows (bf16 hi/lo fused)
        {
            int row = h * 64 + (ht >> 1), rhalf = ht & 1;
            float a2 = sh_a2[row];
            const float* src = X + (size_t)(r0 + row) * DDIM;
            uint8_t* abase = sb + XS + row * 512;
#pragma unroll
            for (int kc = rhalf * 4; kc < rhalf * 4 + 4; kc++) {
#pragma unroll
                for (int qq = 0; qq < 4; qq++) {
                    int d = kc * 16 + qq * 2;
                    float2 v0 = *reinterpret_cast<const float2*>(src + d);
                    float2 v1 = *reinterpret_cast<const float2*>(src + d + 8);
                    uint32_t h0, l0, h1, l1;
                    split2(a2 * v0.x, a2 * v0.y, h0, l0);
                    split2(a2 * v1.x, a2 * v1.y, h1, l1);
                    *reinterpret_cast<uint4*>(abase + ((kc ^ (row & 7)) * 64 + qq * 16)) =
                        make_uint4(h0, h1, l0, l1);
                }
            }
        }

        const int rloc = h * 64 + lw * 16 + rsub;
        const float b2a = sh_b2[rloc];
        const float b2b = sh_b2[rloc + 8];
        const uint8_t* arow1 = sb + XS + rloc * 512;
        const uint8_t* arow2 = arow1 + 8 * 512;

        float o[16][4];
#pragma unroll
        for (int i = 0; i < 16; i++)
#pragma unroll
            for (int j = 0; j < 4; j++) o[i][j] = 0.0f;
        float m_a = -CUDART_INF_F, m_b = -CUDART_INF_F, l_a = 0.0f, l_b = 0.0f;

        for (int kt = t0; kt < t1; kt++) {
            const uint8_t* buf = sb + BUF0 + h * HSTRIDE + (kt & 1) * TBUF;

            CP_WAIT0();
            BARH(h);
            if (kt + 1 < t1) {
                prefetch_half(hbase + ((kt + 1) & 1) * TBUF, kt + 1, ht);
                CP_COMMIT();
            }

            // ---- GEMM1: S[16][32] per warp, 3-term bf16 split, K=128 ----
            float s[4][4];
#pragma unroll
            for (int i = 0; i < 4; i++)
#pragma unroll
                for (int j = 0; j < 4; j++) s[i][j] = 0.0f;

#pragma unroll
            for (int kc = 0; kc < 8; kc++) {
                uint32_t oA = (uint32_t)((kc ^ rsub) * 64 + lq * 16);
                uint4 ua = *reinterpret_cast<const uint4*>(arow1 + oA);
                uint4 ub = *reinterpret_cast<const uint4*>(arow2 + oA);
                uint32_t ah[4] = { ua.x, ub.x, ua.y, ub.y };
                uint32_t al[4] = { ua.z, ub.z, ua.w, ub.w };
                const uint8_t* bbase = buf + kc * 2048 + lane * 16;
#pragma unroll
                for (int nf = 0; nf < 4; nf++) {
                    uint4 bb = *reinterpret_cast<const uint4*>(bbase + nf * 512);
                    mma16816(s[nf], ah, bb.x, bb.y);
                    mma16816(s[nf], ah, bb.z, bb.w);
                    mma16816(s[nf], al, bb.x, bb.y);
                }
            }

            // ---- bias + row max ----
            const float* y2p = (const float*)(buf + B_Y2);
            float mxa = -CUDART_INF_F, mxb = -CUDART_INF_F;
#pragma unroll
            for (int f = 0; f < 4; f++) {
                float2 y2v = *reinterpret_cast<const float2*>(y2p + f * 8 + lq * 2);
                s[f][0] = fmaf(b2a, y2v.x, s[f][0]);
                s[f][1] = fmaf(b2a, y2v.y, s[f][1]);
                s[f][2] = fmaf(b2b, y2v.x, s[f][2]);
                s[f][3] = fmaf(b2b, y2v.y, s[f][3]);
                mxa = fmaxf(mxa, fmaxf(s[f][0], s[f][1]));
                mxb = fmaxf(mxb, fmaxf(s[f][2], s[f][3]));
            }
            mxa = fmaxf(mxa, __shfl_xor_sync(0xffffffffu, mxa, 1));
            mxa = fmaxf(mxa, __shfl_xor_sync(0xffffffffu, mxa, 2));
            mxb = fmaxf(mxb, __shfl_xor_sync(0xffffffffu, mxb, 1));
            mxb = fmaxf(mxb, __shfl_xor_sync(0xffffffffu, mxb, 2));
            float mna = fmaxf(m_a, mxa), mnb = fmaxf(m_b, mxb);

            // ---- rescale only when some row's max advanced ----
            bool upd = (mna > m_a) || (mnb > m_b);
            if (__any_sync(0xffffffffu, upd)) {
                float ala = ex2f(m_a - mna), alb = ex2f(m_b - mnb);
                l_a *= ala; l_b *= alb;
#pragma unroll
                for (int nf = 0; nf < 16; nf++) {
                    o[nf][0] *= ala; o[nf][1] *= ala;
                    o[nf][2] *= alb; o[nf][3] *= alb;
                }
                m_a = mna; m_b = mnb;
            }

            // ---- exp + fp16 pack interleaved with GEMM2 (K=32, 2-term fp16) ----
            float suma = 0.0f, sumb = 0.0f;
            uint32_t ph[8];
            const uint8_t* bbase2 = buf + B_G2 + lane * 16;
#pragma unroll
            for (int f = 0; f < 2; f++) {
                float p0 = ex2f(s[f][0] - m_a), p1 = ex2f(s[f][1] - m_a);
                float p2 = ex2f(s[f][2] - m_b), p3 = ex2f(s[f][3] - m_b);
                suma += p0 + p1; sumb += p2 + p3;
                ph[2 * f]     = pack_f16x2(p0, p1);
                ph[2 * f + 1] = pack_f16x2(p2, p3);
            }
            {   // GEMM2 kc2 = 0
                uint32_t ah[4] = { ph[0], ph[1], ph[2], ph[3] };
#pragma unroll
                for (int nf2 = 0; nf2 < 16; nf2++) {
                    uint4 bb = *reinterpret_cast<const uint4*>(bbase2 + nf2 * 512);
                    mma16816h(o[nf2], ah, bb.x, bb.y);
                    mma16816h(o[nf2], ah, bb.z, bb.w);
                }
            }
#pragma unroll
            for (int f = 2; f < 4; f++) {
                float p0 = ex2f(s[f][0] - m_a), p1 = ex2f(s[f][1] - m_a);
                float p2 = ex2f(s[f][2] - m_b), p3 = ex2f(s[f][3] - m_b);
                suma += p0 + p1; sumb += p2 + p3;
                ph[2 * f]     = pack_f16x2(p0, p1);
                ph[2 * f + 1] = pack_f16x2(p2, p3);
            }
            {   // GEMM2 kc2 = 1
                uint32_t ah[4] = { ph[4], ph[5], ph[6], ph[7] };
                const uint8_t* bk = bbase2 + 8192;
#pragma unroll
                for (int nf2 = 0; nf2 < 16; nf2++) {
                    uint4 bb = *reinterpret_cast<const uint4*>(bk + nf2 * 512);
                    mma16816h(o[nf2], ah, bb.x, bb.y);
                    mma16816h(o[nf2], ah, bb.z, bb.w);
                }
            }

            // ---- deferred l reduction ----
            suma += __shfl_xor_sync(0xffffffffu, suma, 1);
            suma += __shfl_xor_sync(0xffffffffu, suma, 2);
            sumb += __shfl_xor_sync(0xffffffffu, sumb, 1);
            sumb += __shfl_xor_sync(0xffffffffu, sumb, 2);
            l_a += suma;
            l_b += sumb;
        }

        // ---- write segment partials into this rowblock's slot ----
        {
            int ga = r0 + rloc;
            int gbrow = ga + 8;
            if (lq == 0) {
                g_pm[slot * NROWS + ga] = m_a;   g_pl[slot * NROWS + ga] = l_a;
                g_pm[slot * NROWS + gbrow] = m_b; g_pl[slot * NROWS + gbrow] = l_b;
            }
            float* da = g_pO + ((size_t)(slot * NROWS + ga)) * DDIM + lq * 2;
            float* db = g_pO + ((size_t)(slot * NROWS + gbrow)) * DDIM + lq * 2;
#pragma unroll
            for (int nf = 0; nf < 16; nf++) {
                *reinterpret_cast<float2*>(da + nf * 8) = make_float2(o[nf][0], o[nf][1]);
                *reinterpret_cast<float2*>(db + nf * 8) = make_float2(o[nf][2], o[nf][3]);
            }
        }

        u = ue;
    }
}

// ---------------- merge slots + epilogue ----------------
__global__ void gmm_merge_kernel(const float* __restrict__ X, const float* __restrict__ T,
                                 float* __restrict__ out) {
    int row = blockIdx.x * 2 + (threadIdx.x >> 7);
    int d = threadIdx.x & 127;
    float tv = T[row];
    float lm = -0.25f * tv * tv * (BETA_MAX - BETA_MIN) - 0.5f * tv * BETA_MIN;
    float var = fmaxf(1.0f - expf(2.0f * lm), 1e-12f);
    float iv = 1.0f / var;
    float M = -CUDART_INF_F;
    float pm[NSLOT];
#pragma unroll
    for (int s = 0; s < NSLOT; s++) {
        pm[s] = g_pm[s * NROWS + row];
        M = fmaxf(M, pm[s]);
    }
    float L = 0.0f, O = 0.0f;
#pragma unroll
    for (int s = 0; s < NSLOT; s++) {
        if (pm[s] > -1e30f) {
            float w = fexp2(pm[s] - M);
            L += g_pl[s * NROWS + row] * w;
            O += g_pO[((size_t)(s * NROWS + row)) * DDIM + d] * w;
        }
    }
    out[(size_t)row * DDIM + d] = (O / L - X[(size_t)row * DDIM + d]) * iv;
}

// ---------------------------------------------------------------------------
extern "C" void kernel_launch(void* const* d_in, const int* in_sizes, int n_in,
                              void* d_out, int out_size) {
    (void)n_in; (void)out_size;
    const float* x = (const float*)d_in[0];
    const float* t = (const float*)d_in[1];
    const float* y = (const float*)d_in[2];
    float* out = (float*)d_out;

    cudaFuncSetAttribute(gmm_main_kernel,
                         cudaFuncAttributeMaxDynamicSharedMemorySize, SMEM_BYTES);

    gmm_init_kernel<<<NSLOT * NROWS / 1024, 256>>>();
    gmm_prep_kernel<<<TILES_ALL, 256>>>(y);
    gmm_main_kernel<<<NCTA, 256, SMEM_BYTES>>>(x, t);
    gmm_merge_kernel<<<NROWS / 2, 256>>>(x, t, out);
}